// round 11
// baseline (speedup 1.0000x reference)
#include <cuda_runtime.h>
#include <cuda_fp16.h>
#include <cstdint>

// ---------------- problem constants ----------------
#define BATCH   64
#define NSPAT   891            // 9*11*9
#define CDIM    900
#define MTOK    (BATCH*NSPAT)  // 57024
#define MPAD    57088          // 446 * 128
#define RANK    450
#define HID     1800
#define RPAD    512            // 4  * 128
#define HPAD    1920           // 15 * 128
#define CPAD    1024           // 8  * 128

// ---------------- scratch (device globals; zero-initialized at load) ------
__device__ float  g_stats[(size_t)MTOK * 2];         // per-token mean, inv
__device__ float  g_filt[(size_t)MTOK * CDIM];
__device__ __half g_ln2h[(size_t)MPAD * CPAD];
__device__ __half g_a1  [(size_t)MPAD * RPAD];
__device__ __half g_h1  [(size_t)MPAD * HPAD];
__device__ __half g_a2  [(size_t)MPAD * RPAD];
__device__ __half g_u1h [(size_t)RPAD * CPAD];
__device__ __half g_v1h [(size_t)HPAD * RPAD];
__device__ __half g_u2h [(size_t)RPAD * HPAD];
__device__ __half g_v2h [(size_t)CPAD * RPAD];

// ---------------- PTX helpers ----------------
__device__ __forceinline__ uint32_t smem_u32(const void* p) {
    uint32_t a;
    asm("{ .reg .u64 t; cvta.to.shared.u64 t, %1; cvt.u32.u64 %0, t; }" : "=r"(a) : "l"(p));
    return a;
}
#define SWZ128(off) ((off) ^ (((off) >> 3) & 0x70))

__device__ __forceinline__ void cp_async16(uint32_t dst, const void* src) {
    asm volatile("cp.async.cg.shared.global [%0], [%1], 16;" :: "r"(dst), "l"(src) : "memory");
}
__device__ __forceinline__ void cp_commit() {
    asm volatile("cp.async.commit_group;" ::: "memory");
}
__device__ __forceinline__ void cp_wait1() {
    asm volatile("cp.async.wait_group 1;" ::: "memory");
}
__device__ __forceinline__ void ldsm4(uint32_t& r0, uint32_t& r1, uint32_t& r2, uint32_t& r3,
                                      uint32_t addr) {
    asm volatile("ldmatrix.sync.aligned.m8n8.x4.shared.b16 {%0,%1,%2,%3}, [%4];"
                 : "=r"(r0), "=r"(r1), "=r"(r2), "=r"(r3) : "r"(addr));
}
__device__ __forceinline__ void mma16816(float* c, const uint32_t* a, const uint32_t* b) {
    asm volatile(
        "mma.sync.aligned.m16n8k16.row.col.f32.f16.f16.f32 "
        "{%0,%1,%2,%3}, {%4,%5,%6,%7}, {%8,%9}, {%0,%1,%2,%3};"
        : "+f"(c[0]), "+f"(c[1]), "+f"(c[2]), "+f"(c[3])
        : "r"(a[0]), "r"(a[1]), "r"(a[2]), "r"(a[3]), "r"(b[0]), "r"(b[1]));
}

// ---------------- fused weight convert + pad (4 arrays, 1 launch) ---------
#define CVT_S1 (RPAD*CPAD)
#define CVT_S2 (CVT_S1 + HPAD*RPAD)
#define CVT_S3 (CVT_S2 + RPAD*HPAD)
#define CVT_S4 (CVT_S3 + CPAD*RPAD)

__global__ void convert_all(const float* __restrict__ u1, const float* __restrict__ v1,
                            const float* __restrict__ u2, const float* __restrict__ v2,
                            __half* __restrict__ du1, __half* __restrict__ dv1,
                            __half* __restrict__ du2, __half* __restrict__ dv2)
{
    int i = blockIdx.x * blockDim.x + threadIdx.x;
    if (i >= CVT_S4) return;
    const float* src; __half* dst; int N, K, Kpad, j;
    if (i < CVT_S1)      { j = i;          src = u1; dst = du1; N = RANK; K = CDIM; Kpad = CPAD; }
    else if (i < CVT_S2) { j = i - CVT_S1; src = v1; dst = dv1; N = HID;  K = RANK; Kpad = RPAD; }
    else if (i < CVT_S3) { j = i - CVT_S2; src = u2; dst = du2; N = RANK; K = HID;  Kpad = HPAD; }
    else                 { j = i - CVT_S3; src = v2; dst = dv2; N = CDIM; K = RANK; Kpad = RPAD; }
    int n = j / Kpad, k = j - n * Kpad;
    float v = (n < N && k < K) ? src[n * K + k] : 0.f;
    dst[j] = __float2half(v);
}

// ---------------- block reduce (sum, sumsq) ----------------
__device__ __forceinline__ void blockReduce2(float& a, float& b)
{
    #pragma unroll
    for (int o = 16; o > 0; o >>= 1) {
        a += __shfl_down_sync(0xffffffffu, a, o);
        b += __shfl_down_sync(0xffffffffu, b, o);
    }
    __shared__ float sa[4], sb[4];
    int w = threadIdx.x >> 5, l = threadIdx.x & 31;
    if (l == 0) { sa[w] = a; sb[w] = b; }
    __syncthreads();
    if (threadIdx.x == 0) {
        float ta = 0.f, tb = 0.f;
        #pragma unroll
        for (int i = 0; i < 4; i++) { ta += sa[i]; tb += sb[i]; }
        sa[0] = ta; sb[0] = tb;
    }
    __syncthreads();
    a = sa[0]; b = sb[0];
}

// ---------------- LN1 stats only: x -> (mean, inv) per token --------------
__global__ void __launch_bounds__(128) ln1_stats(const float* __restrict__ x,
                                                 float* __restrict__ stats)
{
    size_t row = blockIdx.x;
    const float* xr = x + row * CDIM;
    float s = 0.f, ss = 0.f;
    #pragma unroll
    for (int i = 0; i < 8; i++) {
        int c = threadIdx.x + i * 128;
        float v = (c < CDIM) ? xr[c] : 0.f;
        s += v; ss += v * v;
    }
    blockReduce2(s, ss);
    if (threadIdx.x == 0) {
        float mean = s * (1.f / CDIM);
        float var  = ss * (1.f / CDIM) - mean * mean;
        stats[row * 2]     = mean;
        stats[row * 2 + 1] = rsqrtf(var + 1e-5f);
    }
}

// ---------------- LN2: g_filt -> g_ln2h (fp16, padded to CPAD=1024) -------
__global__ void __launch_bounds__(128) ln2_kernel(const float* __restrict__ in,
                                                  const float* __restrict__ g,
                                                  const float* __restrict__ b,
                                                  __half* __restrict__ out)
{
    size_t row = blockIdx.x;
    const float* xr = in + row * CDIM;
    float vals[8]; float s = 0.f, ss = 0.f;
    #pragma unroll
    for (int i = 0; i < 8; i++) {
        int c = threadIdx.x + i * 128;
        float v = (c < CDIM) ? xr[c] : 0.f;
        vals[i] = v; s += v; ss += v * v;
    }
    blockReduce2(s, ss);
    float mean = s * (1.f / CDIM);
    float var  = ss * (1.f / CDIM) - mean * mean;
    float inv  = rsqrtf(var + 1e-5f);
    __half* orow = out + row * CPAD;
    #pragma unroll
    for (int i = 0; i < 8; i++) {
        int c = threadIdx.x + i * 128;
        if (c < CDIM)      orow[c] = __float2half((vals[i] - mean) * inv * g[c] + b[c]);
        else               orow[c] = __float2half(0.f);
    }
}

// ---------------- fused LN1-normalize + 3D spectral filter ----------------
#define FCH 12
#define FFT_SMEM_FLOATS (891*FCH + 2*495*FCH + 2*(45+121+81) + 2*891 + 2*FCH)

__global__ void __launch_bounds__(256) fft_filter_kernel(const float* __restrict__ xin,
                                                         const float* __restrict__ stats,
                                                         const float* __restrict__ g1,
                                                         const float* __restrict__ b1,
                                                         const float* __restrict__ cw,
                                                         float* __restrict__ yout)
{
    extern __shared__ float sm[];
    float* sR  = sm;
    float* sCr = sR  + 891 * FCH;
    float* sCi = sCr + 495 * FCH;
    float* cD  = sCi + 495 * FCH;
    float* sD  = cD + 45;
    float* cWt = sD + 45;
    float* sWt = cWt + 121;
    float* cHt = sWt + 121;
    float* sHt = cHt + 81;
    float* sSt = sHt + 81;           // 2*891 per-token (mean, inv)
    float* sG  = sSt + 2 * 891;      // FCH gamma
    float* sB  = sG + FCH;           // FCH beta

    int tid = threadIdx.x;
    int b   = blockIdx.y;
    int c0  = blockIdx.x * FCH;

    for (int i = tid; i < 45; i += 256) {
        int kd = i / 9, d = i % 9; float s, c;
        sincospif(2.f * (float)(kd * d) / 9.f, &s, &c);
        cD[i] = c; sD[i] = s;
    }
    for (int i = tid; i < 121; i += 256) {
        int j = i / 11, k = i % 11; float s, c;
        sincospif(2.f * (float)(j * k) / 11.f, &s, &c);
        cWt[i] = c; sWt[i] = s;
    }
    for (int i = tid; i < 81; i += 256) {
        int j = i / 9, k = i % 9; float s, c;
        sincospif(2.f * (float)(j * k) / 9.f, &s, &c);
        cHt[i] = c; sHt[i] = s;
    }
    for (int i = tid; i < 2 * 891; i += 256)
        sSt[i] = stats[(size_t)b * NSPAT * 2 + i];
    if (tid < FCH) { sG[tid] = g1[c0 + tid]; sB[tid] = b1[c0 + tid]; }
    __syncthreads();

    const float* src = xin + ((size_t)b * NSPAT) * CDIM + c0;
    for (int i = tid; i < 891 * FCH; i += 256) {
        int n = i / FCH, cc = i - n * FCH;
        float raw = src[(size_t)n * CDIM + cc];
        sR[i] = (raw - sSt[n * 2]) * sSt[n * 2 + 1] * sG[cc] + sB[cc];
    }
    __syncthreads();

    for (int l = tid; l < 99 * FCH; l += 256) {
        int hw = l / FCH, cc = l - hw * FCH;
        float xr[9];
        #pragma unroll
        for (int d = 0; d < 9; d++) xr[d] = sR[(hw * 9 + d) * FCH + cc];
        #pragma unroll
        for (int kd = 0; kd < 5; kd++) {
            float re = 0.f, im = 0.f;
            #pragma unroll
            for (int d = 0; d < 9; d++) {
                float c = cD[kd * 9 + d], s = sD[kd * 9 + d];
                re += xr[d] * c; im -= xr[d] * s;
            }
            sCr[(hw * 5 + kd) * FCH + cc] = re;
            sCi[(hw * 5 + kd) * FCH + cc] = im;
        }
    }
    __syncthreads();

    for (int l = tid; l < 9 * 5 * FCH; l += 256) {
        int h = l / (5 * FCH); int r = l - h * (5 * FCH); int kd = r / FCH, cc = r - kd * FCH;
        float ar[11], ai[11];
        #pragma unroll
        for (int w = 0; w < 11; w++) {
            int p = ((h * 11 + w) * 5 + kd) * FCH + cc;
            ar[w] = sCr[p]; ai[w] = sCi[p];
        }
        for (int j = 0; j < 11; j++) {
            float re = 0.f, im = 0.f;
            #pragma unroll
            for (int k = 0; k < 11; k++) {
                float c = cWt[j * 11 + k], s = sWt[j * 11 + k];
                re += ar[k] * c + ai[k] * s;
                im += ai[k] * c - ar[k] * s;
            }
            int p = ((h * 11 + j) * 5 + kd) * FCH + cc;
            sCr[p] = re; sCi[p] = im;
        }
    }
    __syncthreads();

    for (int l = tid; l < 11 * 5 * FCH; l += 256) {
        int w = l / (5 * FCH); int r = l - w * (5 * FCH); int kd = r / FCH, cc = r - kd * FCH;
        float ar[9], ai[9];
        #pragma unroll
        for (int h = 0; h < 9; h++) {
            int p = ((h * 11 + w) * 5 + kd) * FCH + cc;
            ar[h] = sCr[p]; ai[h] = sCi[p];
        }
        for (int j = 0; j < 9; j++) {
            float re = 0.f, im = 0.f;
            #pragma unroll
            for (int k = 0; k < 9; k++) {
                float c = cHt[j * 9 + k], s = sHt[j * 9 + k];
                re += ar[k] * c + ai[k] * s;
                im += ai[k] * c - ar[k] * s;
            }
            int p = ((j * 11 + w) * 5 + kd) * FCH + cc;
            sCr[p] = re; sCi[p] = im;
        }
    }
    __syncthreads();

    {
        const float scl = 1.f / 891.f;
        for (int i = tid; i < 495 * FCH; i += 256) {
            int f = i / FCH, cc = i - f * FCH;
            size_t wi = ((size_t)f * CDIM + c0 + cc) * 2;
            float wr = cw[wi] * scl, wim = cw[wi + 1] * scl;
            float xr = sCr[i], xi = sCi[i];
            sCr[i] = xr * wr - xi * wim;
            sCi[i] = xr * wim + xi * wr;
        }
    }
    __syncthreads();

    for (int l = tid; l < 11 * 5 * FCH; l += 256) {
        int w = l / (5 * FCH); int r = l - w * (5 * FCH); int kd = r / FCH, cc = r - kd * FCH;
        float ar[9], ai[9];
        #pragma unroll
        for (int h = 0; h < 9; h++) {
            int p = ((h * 11 + w) * 5 + kd) * FCH + cc;
            ar[h] = sCr[p]; ai[h] = sCi[p];
        }
        for (int j = 0; j < 9; j++) {
            float re = 0.f, im = 0.f;
            #pragma unroll
            for (int k = 0; k < 9; k++) {
                float c = cHt[j * 9 + k], s = sHt[j * 9 + k];
                re += ar[k] * c - ai[k] * s;
                im += ai[k] * c + ar[k] * s;
            }
            int p = ((j * 11 + w) * 5 + kd) * FCH + cc;
            sCr[p] = re; sCi[p] = im;
        }
    }
    __syncthreads();

    for (int l = tid; l < 9 * 5 * FCH; l += 256) {
        int h = l / (5 * FCH); int r = l - h * (5 * FCH); int kd = r / FCH, cc = r - kd * FCH;
        float ar[11], ai[11];
        #pragma unroll
        for (int w = 0; w < 11; w++) {
            int p = ((h * 11 + w) * 5 + kd) * FCH + cc;
            ar[w] = sCr[p]; ai[w] = sCi[p];
        }
        for (int j = 0; j < 11; j++) {
            float re = 0.f, im = 0.f;
            #pragma unroll
            for (int k = 0; k < 11; k++) {
                float c = cWt[j * 11 + k], s = sWt[j * 11 + k];
                re += ar[k] * c - ai[k] * s;
                im += ai[k] * c + ar[k] * s;
            }
            int p = ((h * 11 + j) * 5 + kd) * FCH + cc;
            sCr[p] = re; sCi[p] = im;
        }
    }
    __syncthreads();

    float* dst = yout + ((size_t)b * NSPAT) * CDIM + c0;
    for (int l = tid; l < 99 * FCH; l += 256) {
        int hw = l / FCH, cc = l - hw * FCH;
        float Xr[5], Xi[5];
        #pragma unroll
        for (int kd = 0; kd < 5; kd++) {
            int p = (hw * 5 + kd) * FCH + cc;
            Xr[kd] = sCr[p]; Xi[kd] = sCi[p];
        }
        for (int d = 0; d < 9; d++) {
            float v = Xr[0];
            #pragma unroll
            for (int k = 1; k < 5; k++)
                v += 2.f * (Xr[k] * cD[k * 9 + d] - Xi[k] * sD[k * 9 + d]);
            dst[(size_t)(hw * 9 + d) * CDIM + cc] = v;
        }
    }
}

// ---------------- persistent mma.sync GEMM: C = A(MxK) * B(NxK)^T --------
// R7 mainloop (measured best) + persistent tile loop (grid = 296).
// CTA tile 128x128, BK=64 (SW128), 3-stage cp.async, single sync per K-tile,
// loads before compute, 2 CTAs/SM. 8 warps = 2(M) x 4(N); warp tile 64x32.
#define GS      3
#define STAGEB  32768             // 16KB A + 16KB B
#define GEMM_SMEM (GS*STAGEB)
#define GEMM_GRID 296             // 148 SMs x 2 CTAs

__device__ __forceinline__ void load_stage(
    const __half* __restrict__ A, int lda,
    const __half* __restrict__ B, int ldb,
    int mBase, int nBase, uint32_t data0, int sn, int kt, int tid)
{
    uint32_t sbase = data0 + sn * STAGEB;
    #pragma unroll
    for (int j = 0; j < 8; j++) {
        int ci = tid + j * 256;              // 0..2047
        int v  = ci & 1023;
        int row = v >> 3;
        int cb  = (v & 7) << 4;              // byte col within 128B row
        const __half* g;
        uint32_t dst;
        if (ci < 1024) {
            g   = A + (size_t)(mBase + row) * lda + kt * 64 + (cb >> 1);
            dst = sbase + SWZ128(row * 128 + cb);
        } else {
            g   = B + (size_t)(nBase + row) * ldb + kt * 64 + (cb >> 1);
            dst = sbase + 16384 + SWZ128(row * 128 + cb);
        }
        cp_async16(dst, g);
    }
}

__global__ void __launch_bounds__(256, 2) gemm_mma(
    const __half* __restrict__ A, int lda,
    const __half* __restrict__ B, int ldb,
    __half* outH, int ldo,
    float* outF,
    const float* __restrict__ bias,
    const float* __restrict__ resid,
    int Nvalid, int KT, int epi, int Mvalid,
    int nx, int totalTiles)
{
    extern __shared__ __align__(1024) char smem[];
    uint32_t data0 = smem_u32(smem);

    int tid   = threadIdx.x;
    int lane  = tid & 31;
    int warp  = tid >> 5;
    int wm    = warp >> 2;            // 0..1 -> 64 rows
    int wn    = warp & 3;             // 0..3 -> 32 cols

    // ldmatrix lane geometry
    int mi  = lane >> 3, rin = lane & 7;
    int rowA = wm * 64 + (mi & 1) * 8 + rin;    // + m*16
    int colA = (mi >> 1) * 16;                  // bytes
    int rowB = wn * 32 + (mi >> 1) * 8 + rin;   // + np*16
    int colB = (mi & 1) * 16;

    for (int t = blockIdx.x; t < totalTiles; t += gridDim.x) {
        int nBase = (t % nx) * 128;
        int mBase = (t / nx) * 128;

        float cAcc[4][4][4];
        #pragma unroll
        for (int m = 0; m < 4; m++)
            #pragma unroll
            for (int n = 0; n < 4; n++)
                #pragma unroll
                for (int r = 0; r < 4; r++) cAcc[m][n][r] = 0.f;

        __syncthreads();   // all warps finished reading smem of previous tile

        // prologue: stages 0,1
        load_stage(A, lda, B, ldb, mBase, nBase, data0, 0, 0, tid);
        cp_commit();
        load_stage(A, lda, B, ldb, mBase, nBase, data0, 1, 1, tid);
        cp_commit();

        int s = 0;
        for (int k = 0; k < KT; k++) {
            cp_wait1();               // tile k resident (k+1 may be in flight)
            __syncthreads();          // all warps finished reading slot reused below

            // issue loads for k+2 into slot (k+2)%GS == (k-1)%GS BEFORE compute
            int kn = k + 2;
            if (kn < KT) {
                int sn = s + 2; if (sn >= GS) sn -= GS;
                load_stage(A, lda, B, ldb, mBase, nBase, data0, sn, kn, tid);
            }
            cp_commit();              // uniform group counting

            uint32_t As = data0 + s * STAGEB;
            uint32_t Bs = As + 16384;
            #pragma unroll
            for (int kk = 0; kk < 4; kk++) {
                uint32_t a[4][4];
                #pragma unroll
                for (int m = 0; m < 4; m++) {
                    uint32_t br = (uint32_t)(rowA + m * 16) * 128;
                    uint32_t xv = (br >> 3) & 0x70;
                    ldsm4(a[m][0], a[m][1], a[m][2], a[m][3],
                          As + br + ((kk * 32 + colA) ^ xv));
                }
                uint32_t b[4][2];
                #pragma unroll
                for (int np = 0; np < 2; np++) {
                    uint32_t br = (uint32_t)(rowB + np * 16) * 128;
                    uint32_t xv = (br >> 3) & 0x70;
                    uint32_t r0, r1, r2, r3;
                    ldsm4(r0, r1, r2, r3, Bs + br + ((kk * 32 + colB) ^ xv));
                    b[np * 2][0] = r0; b[np * 2][1] = r1;
                    b[np * 2 + 1][0] = r2; b[np * 2 + 1][1] = r3;
                }
                #pragma unroll
                for (int m = 0; m < 4; m++)
                    #pragma unroll
                    for (int n = 0; n < 4; n++)
                        mma16816(cAcc[m][n], a[m], b[n]);
            }

            s++; if (s == GS) s = 0;
        }

        // epilogue: registers -> global
        int r0 = lane >> 2, c0 = (lane & 3) * 2;
        #pragma unroll
        for (int m = 0; m < 4; m++) {
            #pragma unroll
            for (int n = 0; n < 4; n++) {
                int gnc = nBase + wn * 32 + n * 8 + c0;
                #pragma unroll
                for (int h = 0; h < 2; h++) {
                    int gm = mBase + wm * 64 + m * 16 + r0 + h * 8;
                    float v0 = cAcc[m][n][h * 2 + 0];
                    float v1 = cAcc[m][n][h * 2 + 1];
                    if (epi == 0) {
                        __half2 hv = __floats2half2_rn(v0, v1);
                        *(__half2*)(outH + (size_t)gm * ldo + gnc) = hv;
                    } else if (epi == 1) {
                        float o0 = 0.f, o1 = 0.f;
                        if (gnc < Nvalid) {
                            float tt = v0 + bias[gnc];
                            o0 = 0.5f * tt * (1.f + erff(tt * 0.70710678118654752f));
                        }
                        if (gnc + 1 < Nvalid) {
                            float tt = v1 + bias[gnc + 1];
                            o1 = 0.5f * tt * (1.f + erff(tt * 0.70710678118654752f));
                        }
                        *(__half2*)(outH + (size_t)gm * ldo + gnc) = __floats2half2_rn(o0, o1);
                    } else {
                        if (gm < Mvalid) {
                            if (gnc < Nvalid)
                                outF[(size_t)gm * Nvalid + gnc] =
                                    v0 + bias[gnc] + resid[(size_t)gm * Nvalid + gnc];
                            if (gnc + 1 < Nvalid)
                                outF[(size_t)gm * Nvalid + gnc + 1] =
                                    v1 + bias[gnc + 1] + resid[(size_t)gm * Nvalid + gnc + 1];
                        }
                    }
                }
            }
        }
    }
}

// ---------------- launcher ----------------
extern "C" void kernel_launch(void* const* d_in, const int* in_sizes, int n_in,
                              void* d_out, int out_size)
{
    (void)in_sizes; (void)n_in; (void)out_size;
    const float* x   = (const float*)d_in[0];
    const float* cw  = (const float*)d_in[1];
    const float* g1  = (const float*)d_in[2];
    const float* b1  = (const float*)d_in[3];
    const float* g2  = (const float*)d_in[4];
    const float* b2  = (const float*)d_in[5];
    const float* u1w = (const float*)d_in[6];
    const float* v1w = (const float*)d_in[7];
    const float* v1b = (const float*)d_in[8];
    const float* u2w = (const float*)d_in[9];
    const float* v2w = (const float*)d_in[10];
    const float* v2b = (const float*)d_in[11];
    float* out = (float*)d_out;

    void *p_stats, *p_filt, *p_ln2h, *p_a1, *p_h1, *p_a2, *p_u1, *p_v1, *p_u2, *p_v2;
    cudaGetSymbolAddress(&p_stats, g_stats);
    cudaGetSymbolAddress(&p_filt, g_filt);
    cudaGetSymbolAddress(&p_ln2h, g_ln2h);
    cudaGetSymbolAddress(&p_a1,   g_a1);
    cudaGetSymbolAddress(&p_h1,   g_h1);
    cudaGetSymbolAddress(&p_a2,   g_a2);
    cudaGetSymbolAddress(&p_u1,   g_u1h);
    cudaGetSymbolAddress(&p_v1,   g_v1h);
    cudaGetSymbolAddress(&p_u2,   g_u2h);
    cudaGetSymbolAddress(&p_v2,   g_v2h);

    cudaFuncSetAttribute(fft_filter_kernel, cudaFuncAttributeMaxDynamicSharedMemorySize,
                         FFT_SMEM_FLOATS * 4);
    cudaFuncSetAttribute(gemm_mma, cudaFuncAttributeMaxDynamicSharedMemorySize, GEMM_SMEM);

    convert_all<<<(CVT_S4 + 255) / 256, 256>>>(u1w, v1w, u2w, v2w,
        (__half*)p_u1, (__half*)p_v1, (__half*)p_u2, (__half*)p_v2);

    ln1_stats<<<MTOK, 128>>>(x, (float*)p_stats);

    fft_filter_kernel<<<dim3(CDIM / FCH, BATCH), 256, FFT_SMEM_FLOATS * 4>>>(
        x, (const float*)p_stats, g1, b1, cw, (float*)p_filt);

    ln2_kernel<<<MTOK, 128>>>((const float*)p_filt, g2, b2, (__half*)p_ln2h);

    // z1 = ln2 @ u1^T   (M x 512pad), K: tiles 0..14 (cols 960..1023 all-zero, skipped)
    gemm_mma<<<GEMM_GRID, 256, GEMM_SMEM>>>(
        (const __half*)p_ln2h, CPAD, (const __half*)p_u1, CPAD,
        (__half*)p_a1, RPAD, nullptr, nullptr, nullptr, RANK, 15, 0, MTOK,
        RPAD / 128, (RPAD / 128) * (MPAD / 128));

    // h = gelu(z1 @ v1^T + b)  (M x 1920pad), K = 512pad
    gemm_mma<<<GEMM_GRID, 256, GEMM_SMEM>>>(
        (const __half*)p_a1, RPAD, (const __half*)p_v1, RPAD,
        (__half*)p_h1, HPAD, nullptr, v1b, nullptr, HID, RPAD / 64, 1, MTOK,
        HPAD / 128, (HPAD / 128) * (MPAD / 128));

    // z2 = h @ u2^T   (M x 512pad), K: tiles 0..28 (cols 1856..1919 all-zero, skipped)
    gemm_mma<<<GEMM_GRID, 256, GEMM_SMEM>>>(
        (const __half*)p_h1, HPAD, (const __half*)p_u2, HPAD,
        (__half*)p_a2, RPAD, nullptr, nullptr, nullptr, RANK, 29, 0, MTOK,
        RPAD / 128, (RPAD / 128) * (MPAD / 128));

    // out = z2 @ v2^T + b + x  (M x 1024pad -> 900 valid), K = 512pad
    gemm_mma<<<GEMM_GRID, 256, GEMM_SMEM>>>(
        (const __half*)p_a2, RPAD, (const __half*)p_v2, RPAD,
        nullptr, CDIM, out, v2b, x, CDIM, RPAD / 64, 2, MTOK,
        CPAD / 128, (CPAD / 128) * (MPAD / 128));
}

// round 13
// speedup vs baseline: 1.0723x; 1.0723x over previous
#include <cuda_runtime.h>
#include <cuda_fp16.h>
#include <cstdint>

// ---------------- problem constants ----------------
#define BATCH   64
#define NSPAT   891            // 9*11*9
#define CDIM    900
#define MTOK    (BATCH*NSPAT)  // 57024
#define MPAD    57088          // 446 * 128
#define RANK    450
#define HID     1800
#define RPAD    512            // 4  * 128
#define HPAD    1920           // 15 * 128
#define CPAD    1024           // 8  * 128

// ---------------- scratch (device globals; zero-initialized at load) ------
__device__ float  g_stats[(size_t)MTOK * 2];         // per-token mean, inv
__device__ float  g_filt[(size_t)MTOK * CDIM];
__device__ __half g_ln2h[(size_t)MPAD * CPAD];
__device__ __half g_a1  [(size_t)MPAD * RPAD];
__device__ __half g_h1  [(size_t)MPAD * HPAD];
__device__ __half g_a2  [(size_t)MPAD * RPAD];
__device__ __half g_u1h [(size_t)RPAD * CPAD];
__device__ __half g_v1h [(size_t)HPAD * RPAD];
__device__ __half g_u2h [(size_t)RPAD * HPAD];
__device__ __half g_v2h [(size_t)CPAD * RPAD];

// ---------------- PTX helpers ----------------
__device__ __forceinline__ uint32_t smem_u32(const void* p) {
    uint32_t a;
    asm("{ .reg .u64 t; cvta.to.shared.u64 t, %1; cvt.u32.u64 %0, t; }" : "=r"(a) : "l"(p));
    return a;
}
#define SWZ128(off) ((off) ^ (((off) >> 3) & 0x70))

__device__ __forceinline__ void cp_async16(uint32_t dst, const void* src) {
    asm volatile("cp.async.cg.shared.global [%0], [%1], 16;" :: "r"(dst), "l"(src) : "memory");
}
__device__ __forceinline__ void cp_commit() {
    asm volatile("cp.async.commit_group;" ::: "memory");
}
__device__ __forceinline__ void cp_wait1() {
    asm volatile("cp.async.wait_group 1;" ::: "memory");
}
__device__ __forceinline__ void ldsm4(uint32_t& r0, uint32_t& r1, uint32_t& r2, uint32_t& r3,
                                      uint32_t addr) {
    asm volatile("ldmatrix.sync.aligned.m8n8.x4.shared.b16 {%0,%1,%2,%3}, [%4];"
                 : "=r"(r0), "=r"(r1), "=r"(r2), "=r"(r3) : "r"(addr));
}
__device__ __forceinline__ void mma16816(float* c, const uint32_t* a, const uint32_t* b) {
    asm volatile(
        "mma.sync.aligned.m16n8k16.row.col.f32.f16.f16.f32 "
        "{%0,%1,%2,%3}, {%4,%5,%6,%7}, {%8,%9}, {%0,%1,%2,%3};"
        : "+f"(c[0]), "+f"(c[1]), "+f"(c[2]), "+f"(c[3])
        : "r"(a[0]), "r"(a[1]), "r"(a[2]), "r"(a[3]), "r"(b[0]), "r"(b[1]));
}

// ---------------- fused weight convert + pad (4 arrays, 1 launch) ---------
#define CVT_S1 (RPAD*CPAD)
#define CVT_S2 (CVT_S1 + HPAD*RPAD)
#define CVT_S3 (CVT_S2 + RPAD*HPAD)
#define CVT_S4 (CVT_S3 + CPAD*RPAD)

__global__ void convert_all(const float* __restrict__ u1, const float* __restrict__ v1,
                            const float* __restrict__ u2, const float* __restrict__ v2,
                            __half* __restrict__ du1, __half* __restrict__ dv1,
                            __half* __restrict__ du2, __half* __restrict__ dv2)
{
    int i = blockIdx.x * blockDim.x + threadIdx.x;
    if (i >= CVT_S4) return;
    const float* src; __half* dst; int N, K, Kpad, j;
    if (i < CVT_S1)      { j = i;          src = u1; dst = du1; N = RANK; K = CDIM; Kpad = CPAD; }
    else if (i < CVT_S2) { j = i - CVT_S1; src = v1; dst = dv1; N = HID;  K = RANK; Kpad = RPAD; }
    else if (i < CVT_S3) { j = i - CVT_S2; src = u2; dst = du2; N = RANK; K = HID;  Kpad = HPAD; }
    else                 { j = i - CVT_S3; src = v2; dst = dv2; N = CDIM; K = RANK; Kpad = RPAD; }
    int n = j / Kpad, k = j - n * Kpad;
    float v = (n < N && k < K) ? src[n * K + k] : 0.f;
    dst[j] = __float2half(v);
}

// ---------------- block reduce (sum, sumsq) ----------------
__device__ __forceinline__ void blockReduce2(float& a, float& b)
{
    #pragma unroll
    for (int o = 16; o > 0; o >>= 1) {
        a += __shfl_down_sync(0xffffffffu, a, o);
        b += __shfl_down_sync(0xffffffffu, b, o);
    }
    __shared__ float sa[4], sb[4];
    int w = threadIdx.x >> 5, l = threadIdx.x & 31;
    if (l == 0) { sa[w] = a; sb[w] = b; }
    __syncthreads();
    if (threadIdx.x == 0) {
        float ta = 0.f, tb = 0.f;
        #pragma unroll
        for (int i = 0; i < 4; i++) { ta += sa[i]; tb += sb[i]; }
        sa[0] = ta; sb[0] = tb;
    }
    __syncthreads();
    a = sa[0]; b = sb[0];
}

// ---------------- LN1 stats only: x -> (mean, inv) per token --------------
__global__ void __launch_bounds__(128) ln1_stats(const float* __restrict__ x,
                                                 float* __restrict__ stats)
{
    size_t row = blockIdx.x;
    const float* xr = x + row * CDIM;
    float s = 0.f, ss = 0.f;
    #pragma unroll
    for (int i = 0; i < 8; i++) {
        int c = threadIdx.x + i * 128;
        float v = (c < CDIM) ? xr[c] : 0.f;
        s += v; ss += v * v;
    }
    blockReduce2(s, ss);
    if (threadIdx.x == 0) {
        float mean = s * (1.f / CDIM);
        float var  = ss * (1.f / CDIM) - mean * mean;
        stats[row * 2]     = mean;
        stats[row * 2 + 1] = rsqrtf(var + 1e-5f);
    }
}

// ---------------- LN2: g_filt -> g_ln2h (fp16, padded to CPAD=1024) -------
__global__ void __launch_bounds__(128) ln2_kernel(const float* __restrict__ in,
                                                  const float* __restrict__ g,
                                                  const float* __restrict__ b,
                                                  __half* __restrict__ out)
{
    size_t row = blockIdx.x;
    const float* xr = in + row * CDIM;
    float vals[8]; float s = 0.f, ss = 0.f;
    #pragma unroll
    for (int i = 0; i < 8; i++) {
        int c = threadIdx.x + i * 128;
        float v = (c < CDIM) ? xr[c] : 0.f;
        vals[i] = v; s += v; ss += v * v;
    }
    blockReduce2(s, ss);
    float mean = s * (1.f / CDIM);
    float var  = ss * (1.f / CDIM) - mean * mean;
    float inv  = rsqrtf(var + 1e-5f);
    __half* orow = out + row * CPAD;
    #pragma unroll
    for (int i = 0; i < 8; i++) {
        int c = threadIdx.x + i * 128;
        if (c < CDIM)      orow[c] = __float2half((vals[i] - mean) * inv * g[c] + b[c]);
        else               orow[c] = __float2half(0.f);
    }
}

// ---------------- fused LN1-normalize + 3D spectral filter ----------------
#define FCH 12
#define FFT_SMEM_FLOATS (891*FCH + 2*495*FCH + 2*(45+121+81) + 2*891 + 2*FCH)

__global__ void __launch_bounds__(256) fft_filter_kernel(const float* __restrict__ xin,
                                                         const float* __restrict__ stats,
                                                         const float* __restrict__ g1,
                                                         const float* __restrict__ b1,
                                                         const float* __restrict__ cw,
                                                         float* __restrict__ yout)
{
    extern __shared__ float sm[];
    float* sR  = sm;
    float* sCr = sR  + 891 * FCH;
    float* sCi = sCr + 495 * FCH;
    float* cD  = sCi + 495 * FCH;
    float* sD  = cD + 45;
    float* cWt = sD + 45;
    float* sWt = cWt + 121;
    float* cHt = sWt + 121;
    float* sHt = cHt + 81;
    float* sSt = sHt + 81;           // 2*891 per-token (mean, inv)
    float* sG  = sSt + 2 * 891;      // FCH gamma
    float* sB  = sG + FCH;           // FCH beta

    int tid = threadIdx.x;
    int b   = blockIdx.y;
    int c0  = blockIdx.x * FCH;

    for (int i = tid; i < 45; i += 256) {
        int kd = i / 9, d = i % 9; float s, c;
        sincospif(2.f * (float)(kd * d) / 9.f, &s, &c);
        cD[i] = c; sD[i] = s;
    }
    for (int i = tid; i < 121; i += 256) {
        int j = i / 11, k = i % 11; float s, c;
        sincospif(2.f * (float)(j * k) / 11.f, &s, &c);
        cWt[i] = c; sWt[i] = s;
    }
    for (int i = tid; i < 81; i += 256) {
        int j = i / 9, k = i % 9; float s, c;
        sincospif(2.f * (float)(j * k) / 9.f, &s, &c);
        cHt[i] = c; sHt[i] = s;
    }
    for (int i = tid; i < 2 * 891; i += 256)
        sSt[i] = stats[(size_t)b * NSPAT * 2 + i];
    if (tid < FCH) { sG[tid] = g1[c0 + tid]; sB[tid] = b1[c0 + tid]; }
    __syncthreads();

    const float* src = xin + ((size_t)b * NSPAT) * CDIM + c0;
    for (int i = tid; i < 891 * FCH; i += 256) {
        int n = i / FCH, cc = i - n * FCH;
        float raw = src[(size_t)n * CDIM + cc];
        sR[i] = (raw - sSt[n * 2]) * sSt[n * 2 + 1] * sG[cc] + sB[cc];
    }
    __syncthreads();

    for (int l = tid; l < 99 * FCH; l += 256) {
        int hw = l / FCH, cc = l - hw * FCH;
        float xr[9];
        #pragma unroll
        for (int d = 0; d < 9; d++) xr[d] = sR[(hw * 9 + d) * FCH + cc];
        #pragma unroll
        for (int kd = 0; kd < 5; kd++) {
            float re = 0.f, im = 0.f;
            #pragma unroll
            for (int d = 0; d < 9; d++) {
                float c = cD[kd * 9 + d], s = sD[kd * 9 + d];
                re += xr[d] * c; im -= xr[d] * s;
            }
            sCr[(hw * 5 + kd) * FCH + cc] = re;
            sCi[(hw * 5 + kd) * FCH + cc] = im;
        }
    }
    __syncthreads();

    for (int l = tid; l < 9 * 5 * FCH; l += 256) {
        int h = l / (5 * FCH); int r = l - h * (5 * FCH); int kd = r / FCH, cc = r - kd * FCH;
        float ar[11], ai[11];
        #pragma unroll
        for (int w = 0; w < 11; w++) {
            int p = ((h * 11 + w) * 5 + kd) * FCH + cc;
            ar[w] = sCr[p]; ai[w] = sCi[p];
        }
        for (int j = 0; j < 11; j++) {
            float re = 0.f, im = 0.f;
            #pragma unroll
            for (int k = 0; k < 11; k++) {
                float c = cWt[j * 11 + k], s = sWt[j * 11 + k];
                re += ar[k] * c + ai[k] * s;
                im += ai[k] * c - ar[k] * s;
            }
            int p = ((h * 11 + j) * 5 + kd) * FCH + cc;
            sCr[p] = re; sCi[p] = im;
        }
    }
    __syncthreads();

    for (int l = tid; l < 11 * 5 * FCH; l += 256) {
        int w = l / (5 * FCH); int r = l - w * (5 * FCH); int kd = r / FCH, cc = r - kd * FCH;
        float ar[9], ai[9];
        #pragma unroll
        for (int h = 0; h < 9; h++) {
            int p = ((h * 11 + w) * 5 + kd) * FCH + cc;
            ar[h] = sCr[p]; ai[h] = sCi[p];
        }
        for (int j = 0; j < 9; j++) {
            float re = 0.f, im = 0.f;
            #pragma unroll
            for (int k = 0; k < 9; k++) {
                float c = cHt[j * 9 + k], s = sHt[j * 9 + k];
                re += ar[k] * c + ai[k] * s;
                im += ai[k] * c - ar[k] * s;
            }
            int p = ((j * 11 + w) * 5 + kd) * FCH + cc;
            sCr[p] = re; sCi[p] = im;
        }
    }
    __syncthreads();

    {
        const float scl = 1.f / 891.f;
        for (int i = tid; i < 495 * FCH; i += 256) {
            int f = i / FCH, cc = i - f * FCH;
            size_t wi = ((size_t)f * CDIM + c0 + cc) * 2;
            float wr = cw[wi] * scl, wim = cw[wi + 1] * scl;
            float xr = sCr[i], xi = sCi[i];
            sCr[i] = xr * wr - xi * wim;
            sCi[i] = xr * wim + xi * wr;
        }
    }
    __syncthreads();

    for (int l = tid; l < 11 * 5 * FCH; l += 256) {
        int w = l / (5 * FCH); int r = l - w * (5 * FCH); int kd = r / FCH, cc = r - kd * FCH;
        float ar[9], ai[9];
        #pragma unroll
        for (int h = 0; h < 9; h++) {
            int p = ((h * 11 + w) * 5 + kd) * FCH + cc;
            ar[h] = sCr[p]; ai[h] = sCi[p];
        }
        for (int j = 0; j < 9; j++) {
            float re = 0.f, im = 0.f;
            #pragma unroll
            for (int k = 0; k < 9; k++) {
                float c = cHt[j * 9 + k], s = sHt[j * 9 + k];
                re += ar[k] * c - ai[k] * s;
                im += ai[k] * c + ar[k] * s;
            }
            int p = ((j * 11 + w) * 5 + kd) * FCH + cc;
            sCr[p] = re; sCi[p] = im;
        }
    }
    __syncthreads();

    for (int l = tid; l < 9 * 5 * FCH; l += 256) {
        int h = l / (5 * FCH); int r = l - h * (5 * FCH); int kd = r / FCH, cc = r - kd * FCH;
        float ar[11], ai[11];
        #pragma unroll
        for (int w = 0; w < 11; w++) {
            int p = ((h * 11 + w) * 5 + kd) * FCH + cc;
            ar[w] = sCr[p]; ai[w] = sCi[p];
        }
        for (int j = 0; j < 11; j++) {
            float re = 0.f, im = 0.f;
            #pragma unroll
            for (int k = 0; k < 11; k++) {
                float c = cWt[j * 11 + k], s = sWt[j * 11 + k];
                re += ar[k] * c - ai[k] * s;
                im += ai[k] * c + ar[k] * s;
            }
            int p = ((h * 11 + j) * 5 + kd) * FCH + cc;
            sCr[p] = re; sCi[p] = im;
        }
    }
    __syncthreads();

    float* dst = yout + ((size_t)b * NSPAT) * CDIM + c0;
    for (int l = tid; l < 99 * FCH; l += 256) {
        int hw = l / FCH, cc = l - hw * FCH;
        float Xr[5], Xi[5];
        #pragma unroll
        for (int kd = 0; kd < 5; kd++) {
            int p = (hw * 5 + kd) * FCH + cc;
            Xr[kd] = sCr[p]; Xi[kd] = sCi[p];
        }
        for (int d = 0; d < 9; d++) {
            float v = Xr[0];
            #pragma unroll
            for (int k = 1; k < 5; k++)
                v += 2.f * (Xr[k] * cD[k * 9 + d] - Xi[k] * sD[k * 9 + d]);
            dst[(size_t)(hw * 9 + d) * CDIM + cc] = v;
        }
    }
}

// ---------------- mma.sync GEMM: C = A(MxK) * B(NxK)^T ----------------
// R7 config (measured best): CTA 128x128, BK=64 (SW128), 3-stage cp.async,
// single sync per K-tile, loads before compute, 2 CTAs/SM, per-tile grid.
// 8 warps = 2(M) x 4(N); warp tile 64x32; m16n8k16, fp16 in / fp32 accum.
#define GS      3
#define STAGEB  32768             // 16KB A + 16KB B
#define GEMM_SMEM (GS*STAGEB)

__device__ __forceinline__ void load_stage(
    const __half* __restrict__ A, int lda,
    const __half* __restrict__ B, int ldb,
    int mBase, int nBase, uint32_t data0, int sn, int kt, int tid)
{
    uint32_t sbase = data0 + sn * STAGEB;
    #pragma unroll
    for (int j = 0; j < 8; j++) {
        int ci = tid + j * 256;              // 0..2047
        int v  = ci & 1023;
        int row = v >> 3;
        int cb  = (v & 7) << 4;              // byte col within 128B row
        const __half* g;
        uint32_t dst;
        if (ci < 1024) {
            g   = A + (size_t)(mBase + row) * lda + kt * 64 + (cb >> 1);
            dst = sbase + SWZ128(row * 128 + cb);
        } else {
            g   = B + (size_t)(nBase + row) * ldb + kt * 64 + (cb >> 1);
            dst = sbase + 16384 + SWZ128(row * 128 + cb);
        }
        cp_async16(dst, g);
    }
}

__global__ void __launch_bounds__(256, 2) gemm_mma(
    const __half* __restrict__ A, int lda,
    const __half* __restrict__ B, int ldb,
    __half* outH, int ldo,
    float* outF,
    const float* __restrict__ bias,
    const float* __restrict__ resid,
    int Nvalid, int KT, int epi, int Mvalid)
{
    extern __shared__ __align__(1024) char smem[];
    uint32_t data0 = smem_u32(smem);

    int tid   = threadIdx.x;
    int lane  = tid & 31;
    int warp  = tid >> 5;
    int wm    = warp >> 2;            // 0..1 -> 64 rows
    int wn    = warp & 3;             // 0..3 -> 32 cols
    int nBase = blockIdx.x * 128;     // x = N tile (A-panel L2 reuse)
    int mBase = blockIdx.y * 128;

    // ldmatrix lane geometry
    int mi  = lane >> 3, rin = lane & 7;
    int rowA = wm * 64 + (mi & 1) * 8 + rin;    // + m*16
    int colA = (mi >> 1) * 16;                  // bytes
    int rowB = wn * 32 + (mi >> 1) * 8 + rin;   // + np*16
    int colB = (mi & 1) * 16;

    float cAcc[4][4][4];
    #pragma unroll
    for (int m = 0; m < 4; m++)
        #pragma unroll
        for (int n = 0; n < 4; n++)
            #pragma unroll
            for (int r = 0; r < 4; r++) cAcc[m][n][r] = 0.f;

    // prologue: stages 0,1
    load_stage(A, lda, B, ldb, mBase, nBase, data0, 0, 0, tid);
    cp_commit();
    load_stage(A, lda, B, ldb, mBase, nBase, data0, 1, 1, tid);
    cp_commit();

    int s = 0;
    for (int k = 0; k < KT; k++) {
        cp_wait1();                   // tile k resident (k+1 may be in flight)
        __syncthreads();              // all warps finished reading slot reused below

        // issue loads for k+2 into slot (k+2)%GS == (k-1)%GS BEFORE compute
        int kn = k + 2;
        if (kn < KT) {
            int sn = s + 2; if (sn >= GS) sn -= GS;
            load_stage(A, lda, B, ldb, mBase, nBase, data0, sn, kn, tid);
        }
        cp_commit();                  // uniform group counting

        uint32_t As = data0 + s * STAGEB;
        uint32_t Bs = As + 16384;
        #pragma unroll
        for (int kk = 0; kk < 4; kk++) {
            uint32_t a[4][4];
            #pragma unroll
            for (int m = 0; m < 4; m++) {
                uint32_t br = (uint32_t)(rowA + m * 16) * 128;
                uint32_t xv = (br >> 3) & 0x70;
                ldsm4(a[m][0], a[m][1], a[m][2], a[m][3],
                      As + br + ((kk * 32 + colA) ^ xv));
            }
            uint32_t b[4][2];
            #pragma unroll
            for (int np = 0; np < 2; np++) {
                uint32_t br = (uint32_t)(rowB + np * 16) * 128;
                uint32_t xv = (br >> 3) & 0x70;
                uint32_t r0, r1, r2, r3;
                ldsm4(r0, r1, r2, r3, Bs + br + ((kk * 32 + colB) ^ xv));
                b[np * 2][0] = r0; b[np * 2][1] = r1;
                b[np * 2 + 1][0] = r2; b[np * 2 + 1][1] = r3;
            }
            #pragma unroll
            for (int m = 0; m < 4; m++)
                #pragma unroll
                for (int n = 0; n < 4; n++)
                    mma16816(cAcc[m][n], a[m], b[n]);
        }

        s++; if (s == GS) s = 0;
    }

    // epilogue: registers -> global
    int r0 = lane >> 2, c0 = (lane & 3) * 2;
    #pragma unroll
    for (int m = 0; m < 4; m++) {
        #pragma unroll
        for (int n = 0; n < 4; n++) {
            int gnc = nBase + wn * 32 + n * 8 + c0;
            #pragma unroll
            for (int h = 0; h < 2; h++) {
                int gm = mBase + wm * 64 + m * 16 + r0 + h * 8;
                float v0 = cAcc[m][n][h * 2 + 0];
                float v1 = cAcc[m][n][h * 2 + 1];
                if (epi == 0) {
                    __half2 hv = __floats2half2_rn(v0, v1);
                    *(__half2*)(outH + (size_t)gm * ldo + gnc) = hv;
                } else if (epi == 1) {
                    float o0 = 0.f, o1 = 0.f;
                    if (gnc < Nvalid) {
                        float t = v0 + bias[gnc];
                        o0 = 0.5f * t * (1.f + erff(t * 0.70710678118654752f));
                    }
                    if (gnc + 1 < Nvalid) {
                        float t = v1 + bias[gnc + 1];
                        o1 = 0.5f * t * (1.f + erff(t * 0.70710678118654752f));
                    }
                    *(__half2*)(outH + (size_t)gm * ldo + gnc) = __floats2half2_rn(o0, o1);
                } else {
                    if (gm < Mvalid) {
                        if (gnc < Nvalid)
                            outF[(size_t)gm * Nvalid + gnc] =
                                v0 + bias[gnc] + resid[(size_t)gm * Nvalid + gnc];
                        if (gnc + 1 < Nvalid)
                            outF[(size_t)gm * Nvalid + gnc + 1] =
                                v1 + bias[gnc + 1] + resid[(size_t)gm * Nvalid + gnc + 1];
                    }
                }
            }
        }
    }
}

// ---------------- launcher ----------------
extern "C" void kernel_launch(void* const* d_in, const int* in_sizes, int n_in,
                              void* d_out, int out_size)
{
    (void)in_sizes; (void)n_in; (void)out_size;
    const float* x   = (const float*)d_in[0];
    const float* cw  = (const float*)d_in[1];
    const float* g1  = (const float*)d_in[2];
    const float* b1  = (const float*)d_in[3];
    const float* g2  = (const float*)d_in[4];
    const float* b2  = (const float*)d_in[5];
    const float* u1w = (const float*)d_in[6];
    const float* v1w = (const float*)d_in[7];
    const float* v1b = (const float*)d_in[8];
    const float* u2w = (const float*)d_in[9];
    const float* v2w = (const float*)d_in[10];
    const float* v2b = (const float*)d_in[11];
    float* out = (float*)d_out;

    void *p_stats, *p_filt, *p_ln2h, *p_a1, *p_h1, *p_a2, *p_u1, *p_v1, *p_u2, *p_v2;
    cudaGetSymbolAddress(&p_stats, g_stats);
    cudaGetSymbolAddress(&p_filt, g_filt);
    cudaGetSymbolAddress(&p_ln2h, g_ln2h);
    cudaGetSymbolAddress(&p_a1,   g_a1);
    cudaGetSymbolAddress(&p_h1,   g_h1);
    cudaGetSymbolAddress(&p_a2,   g_a2);
    cudaGetSymbolAddress(&p_u1,   g_u1h);
    cudaGetSymbolAddress(&p_v1,   g_v1h);
    cudaGetSymbolAddress(&p_u2,   g_u2h);
    cudaGetSymbolAddress(&p_v2,   g_v2h);

    cudaFuncSetAttribute(fft_filter_kernel, cudaFuncAttributeMaxDynamicSharedMemorySize,
                         FFT_SMEM_FLOATS * 4);
    cudaFuncSetAttribute(gemm_mma, cudaFuncAttributeMaxDynamicSharedMemorySize, GEMM_SMEM);

    convert_all<<<(CVT_S4 + 255) / 256, 256>>>(u1w, v1w, u2w, v2w,
        (__half*)p_u1, (__half*)p_v1, (__half*)p_u2, (__half*)p_v2);

    ln1_stats<<<MTOK, 128>>>(x, (float*)p_stats);

    fft_filter_kernel<<<dim3(CDIM / FCH, BATCH), 256, FFT_SMEM_FLOATS * 4>>>(
        x, (const float*)p_stats, g1, b1, cw, (float*)p_filt);

    ln2_kernel<<<MTOK, 128>>>((const float*)p_filt, g2, b2, (__half*)p_ln2h);

    // z1 = ln2 @ u1^T   (M x 512pad), K: 15 tiles (cols 960..1023 all-zero, skipped)
    gemm_mma<<<dim3(RPAD / 128, MPAD / 128), 256, GEMM_SMEM>>>(
        (const __half*)p_ln2h, CPAD, (const __half*)p_u1, CPAD,
        (__half*)p_a1, RPAD, nullptr, nullptr, nullptr, RANK, 15, 0, MTOK);

    // h = gelu(z1 @ v1^T + b)  (M x 1920pad), K = 512pad
    gemm_mma<<<dim3(HPAD / 128, MPAD / 128), 256, GEMM_SMEM>>>(
        (const __half*)p_a1, RPAD, (const __half*)p_v1, RPAD,
        (__half*)p_h1, HPAD, nullptr, v1b, nullptr, HID, RPAD / 64, 1, MTOK);

    // z2 = h @ u2^T   (M x 512pad), K: 29 tiles (cols 1856..1919 all-zero, skipped)
    gemm_mma<<<dim3(RPAD / 128, MPAD / 128), 256, GEMM_SMEM>>>(
        (const __half*)p_h1, HPAD, (const __half*)p_u2, HPAD,
        (__half*)p_a2, RPAD, nullptr, nullptr, nullptr, RANK, 29, 0, MTOK);

    // out = z2 @ v2^T + b + x  (M x 1024pad -> 900 valid), K = 512pad
    gemm_mma<<<dim3(CPAD / 128, MPAD / 128), 256, GEMM_SMEM>>>(
        (const __half*)p_a2, RPAD, (const __half*)p_v2, RPAD,
        nullptr, CDIM, out, v2b, x, CDIM, RPAD / 64, 2, MTOK);
}

// round 15
// speedup vs baseline: 1.2639x; 1.1787x over previous
#include <cuda_runtime.h>
#include <cuda_fp16.h>
#include <cstdint>

// ---------------- problem constants ----------------
#define BATCH   64
#define NSPAT   891            // 9*11*9
#define CDIM    900
#define MTOK    (BATCH*NSPAT)  // 57024
#define MPAD    57088          // 446 * 128
#define RANK    450
#define HID     1800
#define RPAD    512            // 4  * 128
#define HPAD    1920           // 15 * 128
#define CPAD    1024           // 8  * 128

// ---------------- scratch (device globals; zero-initialized at load) ------
__device__ float  g_stats[(size_t)MTOK * 2];         // per-token mean, inv
__device__ float  g_filt[(size_t)MTOK * CDIM];
__device__ __half g_ln2h[(size_t)MPAD * CPAD];
__device__ __half g_a1  [(size_t)MPAD * RPAD];
__device__ __half g_h1  [(size_t)MPAD * HPAD];
__device__ __half g_a2  [(size_t)MPAD * RPAD];
__device__ __half g_u1h [(size_t)RPAD * CPAD];
__device__ __half g_v1h [(size_t)HPAD * RPAD];
__device__ __half g_u2h [(size_t)RPAD * HPAD];
__device__ __half g_v2h [(size_t)CPAD * RPAD];

// ---------------- PTX helpers ----------------
__device__ __forceinline__ uint32_t smem_u32(const void* p) {
    uint32_t a;
    asm("{ .reg .u64 t; cvta.to.shared.u64 t, %1; cvt.u32.u64 %0, t; }" : "=r"(a) : "l"(p));
    return a;
}
#define SWZ128(off) ((off) ^ (((off) >> 3) & 0x70))

__device__ __forceinline__ void cp_async16(uint32_t dst, const void* src) {
    asm volatile("cp.async.cg.shared.global [%0], [%1], 16;" :: "r"(dst), "l"(src) : "memory");
}
__device__ __forceinline__ void cp_commit() {
    asm volatile("cp.async.commit_group;" ::: "memory");
}
__device__ __forceinline__ void cp_wait1() {
    asm volatile("cp.async.wait_group 1;" ::: "memory");
}
__device__ __forceinline__ void ldsm4(uint32_t& r0, uint32_t& r1, uint32_t& r2, uint32_t& r3,
                                      uint32_t addr) {
    asm volatile("ldmatrix.sync.aligned.m8n8.x4.shared.b16 {%0,%1,%2,%3}, [%4];"
                 : "=r"(r0), "=r"(r1), "=r"(r2), "=r"(r3) : "r"(addr));
}
__device__ __forceinline__ void mma16816(float* c, const uint32_t* a, const uint32_t* b) {
    asm volatile(
        "mma.sync.aligned.m16n8k16.row.col.f32.f16.f16.f32 "
        "{%0,%1,%2,%3}, {%4,%5,%6,%7}, {%8,%9}, {%0,%1,%2,%3};"
        : "+f"(c[0]), "+f"(c[1]), "+f"(c[2]), "+f"(c[3])
        : "r"(a[0]), "r"(a[1]), "r"(a[2]), "r"(a[3]), "r"(b[0]), "r"(b[1]));
}

// ---------------- fused weight convert + pad (4 arrays, 1 launch) ---------
#define CVT_S1 (RPAD*CPAD)
#define CVT_S2 (CVT_S1 + HPAD*RPAD)
#define CVT_S3 (CVT_S2 + RPAD*HPAD)
#define CVT_S4 (CVT_S3 + CPAD*RPAD)

__global__ void convert_all(const float* __restrict__ u1, const float* __restrict__ v1,
                            const float* __restrict__ u2, const float* __restrict__ v2,
                            __half* __restrict__ du1, __half* __restrict__ dv1,
                            __half* __restrict__ du2, __half* __restrict__ dv2)
{
    int i = blockIdx.x * blockDim.x + threadIdx.x;
    if (i >= CVT_S4) return;
    const float* src; __half* dst; int N, K, Kpad, j;
    if (i < CVT_S1)      { j = i;          src = u1; dst = du1; N = RANK; K = CDIM; Kpad = CPAD; }
    else if (i < CVT_S2) { j = i - CVT_S1; src = v1; dst = dv1; N = HID;  K = RANK; Kpad = RPAD; }
    else if (i < CVT_S3) { j = i - CVT_S2; src = u2; dst = du2; N = RANK; K = HID;  Kpad = HPAD; }
    else                 { j = i - CVT_S3; src = v2; dst = dv2; N = CDIM; K = RANK; Kpad = RPAD; }
    int n = j / Kpad, k = j - n * Kpad;
    float v = (n < N && k < K) ? src[n * K + k] : 0.f;
    dst[j] = __float2half(v);
}

// ---------------- block reduce (sum, sumsq) ----------------
__device__ __forceinline__ void blockReduce2(float& a, float& b)
{
    #pragma unroll
    for (int o = 16; o > 0; o >>= 1) {
        a += __shfl_down_sync(0xffffffffu, a, o);
        b += __shfl_down_sync(0xffffffffu, b, o);
    }
    __shared__ float sa[4], sb[4];
    int w = threadIdx.x >> 5, l = threadIdx.x & 31;
    if (l == 0) { sa[w] = a; sb[w] = b; }
    __syncthreads();
    if (threadIdx.x == 0) {
        float ta = 0.f, tb = 0.f;
        #pragma unroll
        for (int i = 0; i < 4; i++) { ta += sa[i]; tb += sb[i]; }
        sa[0] = ta; sb[0] = tb;
    }
    __syncthreads();
    a = sa[0]; b = sb[0];
}

// ---------------- LN1 stats only ----------------
__global__ void __launch_bounds__(128) ln1_stats(const float* __restrict__ x,
                                                 float* __restrict__ stats)
{
    size_t row = blockIdx.x;
    const float* xr = x + row * CDIM;
    float s = 0.f, ss = 0.f;
    #pragma unroll
    for (int i = 0; i < 8; i++) {
        int c = threadIdx.x + i * 128;
        float v = (c < CDIM) ? xr[c] : 0.f;
        s += v; ss += v * v;
    }
    blockReduce2(s, ss);
    if (threadIdx.x == 0) {
        float mean = s * (1.f / CDIM);
        float var  = ss * (1.f / CDIM) - mean * mean;
        stats[row * 2]     = mean;
        stats[row * 2 + 1] = rsqrtf(var + 1e-5f);
    }
}

// ---------------- LN2 ----------------
__global__ void __launch_bounds__(128) ln2_kernel(const float* __restrict__ in,
                                                  const float* __restrict__ g,
                                                  const float* __restrict__ b,
                                                  __half* __restrict__ out)
{
    size_t row = blockIdx.x;
    const float* xr = in + row * CDIM;
    float vals[8]; float s = 0.f, ss = 0.f;
    #pragma unroll
    for (int i = 0; i < 8; i++) {
        int c = threadIdx.x + i * 128;
        float v = (c < CDIM) ? xr[c] : 0.f;
        vals[i] = v; s += v; ss += v * v;
    }
    blockReduce2(s, ss);
    float mean = s * (1.f / CDIM);
    float var  = ss * (1.f / CDIM) - mean * mean;
    float inv  = rsqrtf(var + 1e-5f);
    __half* orow = out + row * CPAD;
    #pragma unroll
    for (int i = 0; i < 8; i++) {
        int c = threadIdx.x + i * 128;
        if (c < CDIM)      orow[c] = __float2half((vals[i] - mean) * inv * g[c] + b[c]);
        else               orow[c] = __float2half(0.f);
    }
}

// ---------------- fused LN1-normalize + 3D spectral filter ----------------
// Symmetric DFT forms: fold k<->N-k input pairs, share partials for j<->N-j
// output pairs. ~2.7x fewer FMAs than naive DFT; same smem layout/sync.
#define FCH 12
#define FFT_SMEM_FLOATS (891*FCH + 2*495*FCH + 2*(45+121+81) + 2*891 + 2*FCH)

__global__ void __launch_bounds__(256) fft_filter_kernel(const float* __restrict__ xin,
                                                         const float* __restrict__ stats,
                                                         const float* __restrict__ g1,
                                                         const float* __restrict__ b1,
                                                         const float* __restrict__ cw,
                                                         float* __restrict__ yout)
{
    extern __shared__ float sm[];
    float* sR  = sm;
    float* sCr = sR  + 891 * FCH;
    float* sCi = sCr + 495 * FCH;
    float* cD  = sCi + 495 * FCH;
    float* sD  = cD + 45;
    float* cWt = sD + 45;
    float* sWt = cWt + 121;
    float* cHt = sWt + 121;
    float* sHt = cHt + 81;
    float* sSt = sHt + 81;           // 2*891 per-token (mean, inv)
    float* sG  = sSt + 2 * 891;      // FCH gamma
    float* sB  = sG + FCH;           // FCH beta

    int tid = threadIdx.x;
    int b   = blockIdx.y;
    int c0  = blockIdx.x * FCH;

    for (int i = tid; i < 45; i += 256) {
        int kd = i / 9, d = i % 9; float s, c;
        sincospif(2.f * (float)(kd * d) / 9.f, &s, &c);
        cD[i] = c; sD[i] = s;
    }
    for (int i = tid; i < 121; i += 256) {
        int j = i / 11, k = i % 11; float s, c;
        sincospif(2.f * (float)(j * k) / 11.f, &s, &c);
        cWt[i] = c; sWt[i] = s;
    }
    for (int i = tid; i < 81; i += 256) {
        int j = i / 9, k = i % 9; float s, c;
        sincospif(2.f * (float)(j * k) / 9.f, &s, &c);
        cHt[i] = c; sHt[i] = s;
    }
    for (int i = tid; i < 2 * 891; i += 256)
        sSt[i] = stats[(size_t)b * NSPAT * 2 + i];
    if (tid < FCH) { sG[tid] = g1[c0 + tid]; sB[tid] = b1[c0 + tid]; }
    __syncthreads();

    const float* src = xin + ((size_t)b * NSPAT) * CDIM + c0;
    for (int i = tid; i < 891 * FCH; i += 256) {
        int n = i / FCH, cc = i - n * FCH;
        float raw = src[(size_t)n * CDIM + cc];
        sR[i] = (raw - sSt[n * 2]) * sSt[n * 2 + 1] * sG[cc] + sB[cc];
    }
    __syncthreads();

    // S1: rfft along D (real 9 -> 5 complex), folded d<->9-d
    for (int l = tid; l < 99 * FCH; l += 256) {
        int hw = l / FCH, cc = l - hw * FCH;
        float xr[9];
        #pragma unroll
        for (int d = 0; d < 9; d++) xr[d] = sR[(hw * 9 + d) * FCH + cc];
        float sp[4], smd[4];
        #pragma unroll
        for (int i = 0; i < 4; i++) { sp[i] = xr[i + 1] + xr[8 - i]; smd[i] = xr[i + 1] - xr[8 - i]; }
        #pragma unroll
        for (int kd = 0; kd < 5; kd++) {
            float re = xr[0], im = 0.f;
            #pragma unroll
            for (int i = 0; i < 4; i++) {
                re += sp[i]  * cD[kd * 9 + i + 1];
                im -= smd[i] * sD[kd * 9 + i + 1];
            }
            sCr[(hw * 5 + kd) * FCH + cc] = re;
            sCi[(hw * 5 + kd) * FCH + cc] = im;
        }
    }
    __syncthreads();

    // S2: forward FFT along W (11 pt), double-folded
    for (int l = tid; l < 9 * 5 * FCH; l += 256) {
        int h = l / (5 * FCH); int r = l - h * (5 * FCH); int kd = r / FCH, cc = r - kd * FCH;
        float ar[11], ai[11];
        #pragma unroll
        for (int w = 0; w < 11; w++) {
            int p = ((h * 11 + w) * 5 + kd) * FCH + cc;
            ar[w] = sCr[p]; ai[w] = sCi[p];
        }
        float arp[5], arm[5], aip[5], aim[5];
        #pragma unroll
        for (int k = 0; k < 5; k++) {
            arp[k] = ar[k + 1] + ar[10 - k]; arm[k] = ar[k + 1] - ar[10 - k];
            aip[k] = ai[k + 1] + ai[10 - k]; aim[k] = ai[k + 1] - ai[10 - k];
        }
        {   // j = 0
            float re0 = ar[0] + arp[0] + arp[1] + arp[2] + arp[3] + arp[4];
            float im0 = ai[0] + aip[0] + aip[1] + aip[2] + aip[3] + aip[4];
            int p = ((h * 11 + 0) * 5 + kd) * FCH + cc;
            sCr[p] = re0; sCi[p] = im0;
        }
        #pragma unroll
        for (int jp = 1; jp <= 5; jp++) {
            float A = ar[0], C = ai[0], B = 0.f, D = 0.f;
            #pragma unroll
            for (int k = 1; k <= 5; k++) {
                float c = cWt[jp * 11 + k], s = sWt[jp * 11 + k];
                A += arp[k - 1] * c;  D += arm[k - 1] * s;
                C += aip[k - 1] * c;  B += aim[k - 1] * s;
            }
            int p1 = ((h * 11 + jp) * 5 + kd) * FCH + cc;
            int p2 = ((h * 11 + (11 - jp)) * 5 + kd) * FCH + cc;
            sCr[p1] = A + B; sCi[p1] = C - D;    // forward: re=A+B, im=C-D
            sCr[p2] = A - B; sCi[p2] = C + D;
        }
    }
    __syncthreads();

    // S3: forward FFT along H (9 pt), double-folded
    for (int l = tid; l < 11 * 5 * FCH; l += 256) {
        int w = l / (5 * FCH); int r = l - w * (5 * FCH); int kd = r / FCH, cc = r - kd * FCH;
        float ar[9], ai[9];
        #pragma unroll
        for (int h = 0; h < 9; h++) {
            int p = ((h * 11 + w) * 5 + kd) * FCH + cc;
            ar[h] = sCr[p]; ai[h] = sCi[p];
        }
        float arp[4], arm[4], aip[4], aim[4];
        #pragma unroll
        for (int k = 0; k < 4; k++) {
            arp[k] = ar[k + 1] + ar[8 - k]; arm[k] = ar[k + 1] - ar[8 - k];
            aip[k] = ai[k + 1] + ai[8 - k]; aim[k] = ai[k + 1] - ai[8 - k];
        }
        {   // j = 0
            float re0 = ar[0] + arp[0] + arp[1] + arp[2] + arp[3];
            float im0 = ai[0] + aip[0] + aip[1] + aip[2] + aip[3];
            int p = ((0 * 11 + w) * 5 + kd) * FCH + cc;
            sCr[p] = re0; sCi[p] = im0;
        }
        #pragma unroll
        for (int jp = 1; jp <= 4; jp++) {
            float A = ar[0], C = ai[0], B = 0.f, D = 0.f;
            #pragma unroll
            for (int k = 1; k <= 4; k++) {
                float c = cHt[jp * 9 + k], s = sHt[jp * 9 + k];
                A += arp[k - 1] * c;  D += arm[k - 1] * s;
                C += aip[k - 1] * c;  B += aim[k - 1] * s;
            }
            int p1 = ((jp * 11 + w) * 5 + kd) * FCH + cc;
            int p2 = (((9 - jp) * 11 + w) * 5 + kd) * FCH + cc;
            sCr[p1] = A + B; sCi[p1] = C - D;
            sCr[p2] = A - B; sCi[p2] = C + D;
        }
    }
    __syncthreads();

    // weight multiply (ortho 1/891 folded in)
    {
        const float scl = 1.f / 891.f;
        for (int i = tid; i < 495 * FCH; i += 256) {
            int f = i / FCH, cc = i - f * FCH;
            size_t wi = ((size_t)f * CDIM + c0 + cc) * 2;
            float wr = cw[wi] * scl, wim = cw[wi + 1] * scl;
            float xr = sCr[i], xi = sCi[i];
            sCr[i] = xr * wr - xi * wim;
            sCi[i] = xr * wim + xi * wr;
        }
    }
    __syncthreads();

    // inverse FFT along H (sign-flipped combine)
    for (int l = tid; l < 11 * 5 * FCH; l += 256) {
        int w = l / (5 * FCH); int r = l - w * (5 * FCH); int kd = r / FCH, cc = r - kd * FCH;
        float ar[9], ai[9];
        #pragma unroll
        for (int h = 0; h < 9; h++) {
            int p = ((h * 11 + w) * 5 + kd) * FCH + cc;
            ar[h] = sCr[p]; ai[h] = sCi[p];
        }
        float arp[4], arm[4], aip[4], aim[4];
        #pragma unroll
        for (int k = 0; k < 4; k++) {
            arp[k] = ar[k + 1] + ar[8 - k]; arm[k] = ar[k + 1] - ar[8 - k];
            aip[k] = ai[k + 1] + ai[8 - k]; aim[k] = ai[k + 1] - ai[8 - k];
        }
        {
            float re0 = ar[0] + arp[0] + arp[1] + arp[2] + arp[3];
            float im0 = ai[0] + aip[0] + aip[1] + aip[2] + aip[3];
            int p = ((0 * 11 + w) * 5 + kd) * FCH + cc;
            sCr[p] = re0; sCi[p] = im0;
        }
        #pragma unroll
        for (int jp = 1; jp <= 4; jp++) {
            float A = ar[0], C = ai[0], B = 0.f, D = 0.f;
            #pragma unroll
            for (int k = 1; k <= 4; k++) {
                float c = cHt[jp * 9 + k], s = sHt[jp * 9 + k];
                A += arp[k - 1] * c;  D += arm[k - 1] * s;
                C += aip[k - 1] * c;  B += aim[k - 1] * s;
            }
            int p1 = ((jp * 11 + w) * 5 + kd) * FCH + cc;
            int p2 = (((9 - jp) * 11 + w) * 5 + kd) * FCH + cc;
            sCr[p1] = A - B; sCi[p1] = C + D;    // inverse: re=A-B, im=C+D
            sCr[p2] = A + B; sCi[p2] = C - D;
        }
    }
    __syncthreads();

    // inverse FFT along W (sign-flipped combine)
    for (int l = tid; l < 9 * 5 * FCH; l += 256) {
        int h = l / (5 * FCH); int r = l - h * (5 * FCH); int kd = r / FCH, cc = r - kd * FCH;
        float ar[11], ai[11];
        #pragma unroll
        for (int w = 0; w < 11; w++) {
            int p = ((h * 11 + w) * 5 + kd) * FCH + cc;
            ar[w] = sCr[p]; ai[w] = sCi[p];
        }
        float arp[5], arm[5], aip[5], aim[5];
        #pragma unroll
        for (int k = 0; k < 5; k++) {
            arp[k] = ar[k + 1] + ar[10 - k]; arm[k] = ar[k + 1] - ar[10 - k];
            aip[k] = ai[k + 1] + ai[10 - k]; aim[k] = ai[k + 1] - ai[10 - k];
        }
        {
            float re0 = ar[0] + arp[0] + arp[1] + arp[2] + arp[3] + arp[4];
            float im0 = ai[0] + aip[0] + aip[1] + aip[2] + aip[3] + aip[4];
            int p = ((h * 11 + 0) * 5 + kd) * FCH + cc;
            sCr[p] = re0; sCi[p] = im0;
        }
        #pragma unroll
        for (int jp = 1; jp <= 5; jp++) {
            float A = ar[0], C = ai[0], B = 0.f, D = 0.f;
            #pragma unroll
            for (int k = 1; k <= 5; k++) {
                float c = cWt[jp * 11 + k], s = sWt[jp * 11 + k];
                A += arp[k - 1] * c;  D += arm[k - 1] * s;
                C += aip[k - 1] * c;  B += aim[k - 1] * s;
            }
            int p1 = ((h * 11 + jp) * 5 + kd) * FCH + cc;
            int p2 = ((h * 11 + (11 - jp)) * 5 + kd) * FCH + cc;
            sCr[p1] = A - B; sCi[p1] = C + D;
            sCr[p2] = A + B; sCi[p2] = C - D;
        }
    }
    __syncthreads();

    // irfft along D -> global, folded d<->9-d
    float* dst = yout + ((size_t)b * NSPAT) * CDIM + c0;
    for (int l = tid; l < 99 * FCH; l += 256) {
        int hw = l / FCH, cc = l - hw * FCH;
        float Xr[5], Xi[5];
        #pragma unroll
        for (int kd = 0; kd < 5; kd++) {
            int p = (hw * 5 + kd) * FCH + cc;
            Xr[kd] = sCr[p]; Xi[kd] = sCi[p];
        }
        float t0 = Xr[0];
        dst[(size_t)(hw * 9 + 0) * CDIM + cc] =
            t0 + 2.f * (Xr[1] + Xr[2] + Xr[3] + Xr[4]);
        #pragma unroll
        for (int dp = 1; dp <= 4; dp++) {
            float P = 0.f, Q = 0.f;
            #pragma unroll
            for (int k = 1; k <= 4; k++) {
                P += Xr[k] * cD[k * 9 + dp];
                Q += Xi[k] * sD[k * 9 + dp];
            }
            dst[(size_t)(hw * 9 + dp) * CDIM + cc]       = t0 + 2.f * (P - Q);
            dst[(size_t)(hw * 9 + (9 - dp)) * CDIM + cc] = t0 + 2.f * (P + Q);
        }
    }
}

// ---------------- mma.sync GEMM (R7/R13 config, measured best) -----------
#define GS      3
#define STAGEB  32768             // 16KB A + 16KB B
#define GEMM_SMEM (GS*STAGEB)

__device__ __forceinline__ void load_stage(
    const __half* __restrict__ A, int lda,
    const __half* __restrict__ B, int ldb,
    int mBase, int nBase, uint32_t data0, int sn, int kt, int tid)
{
    uint32_t sbase = data0 + sn * STAGEB;
    #pragma unroll
    for (int j = 0; j < 8; j++) {
        int ci = tid + j * 256;              // 0..2047
        int v  = ci & 1023;
        int row = v >> 3;
        int cb  = (v & 7) << 4;              // byte col within 128B row
        const __half* g;
        uint32_t dst;
        if (ci < 1024) {
            g   = A + (size_t)(mBase + row) * lda + kt * 64 + (cb >> 1);
            dst = sbase + SWZ128(row * 128 + cb);
        } else {
            g   = B + (size_t)(nBase + row) * ldb + kt * 64 + (cb >> 1);
            dst = sbase + 16384 + SWZ128(row * 128 + cb);
        }
        cp_async16(dst, g);
    }
}

__global__ void __launch_bounds__(256, 2) gemm_mma(
    const __half* __restrict__ A, int lda,
    const __half* __restrict__ B, int ldb,
    __half* outH, int ldo,
    float* outF,
    const float* __restrict__ bias,
    const float* __restrict__ resid,
    int Nvalid, int KT, int epi, int Mvalid)
{
    extern __shared__ __align__(1024) char smem[];
    uint32_t data0 = smem_u32(smem);

    int tid   = threadIdx.x;
    int lane  = tid & 31;
    int warp  = tid >> 5;
    int wm    = warp >> 2;            // 0..1 -> 64 rows
    int wn    = warp & 3;             // 0..3 -> 32 cols
    int nBase = blockIdx.x * 128;     // x = N tile (A-panel L2 reuse)
    int mBase = blockIdx.y * 128;

    // ldmatrix lane geometry
    int mi  = lane >> 3, rin = lane & 7;
    int rowA = wm * 64 + (mi & 1) * 8 + rin;    // + m*16
    int colA = (mi >> 1) * 16;                  // bytes
    int rowB = wn * 32 + (mi >> 1) * 8 + rin;   // + np*16
    int colB = (mi & 1) * 16;

    float cAcc[4][4][4];
    #pragma unroll
    for (int m = 0; m < 4; m++)
        #pragma unroll
        for (int n = 0; n < 4; n++)
            #pragma unroll
            for (int r = 0; r < 4; r++) cAcc[m][n][r] = 0.f;

    // prologue: stages 0,1
    load_stage(A, lda, B, ldb, mBase, nBase, data0, 0, 0, tid);
    cp_commit();
    load_stage(A, lda, B, ldb, mBase, nBase, data0, 1, 1, tid);
    cp_commit();

    int s = 0;
    for (int k = 0; k < KT; k++) {
        cp_wait1();                   // tile k resident (k+1 may be in flight)
        __syncthreads();              // all warps finished reading slot reused below

        int kn = k + 2;
        if (kn < KT) {
            int sn = s + 2; if (sn >= GS) sn -= GS;
            load_stage(A, lda, B, ldb, mBase, nBase, data0, sn, kn, tid);
        }
        cp_commit();                  // uniform group counting

        uint32_t As = data0 + s * STAGEB;
        uint32_t Bs = As + 16384;
        #pragma unroll
        for (int kk = 0; kk < 4; kk++) {
            uint32_t a[4][4];
            #pragma unroll
            for (int m = 0; m < 4; m++) {
                uint32_t br = (uint32_t)(rowA + m * 16) * 128;
                uint32_t xv = (br >> 3) & 0x70;
                ldsm4(a[m][0], a[m][1], a[m][2], a[m][3],
                      As + br + ((kk * 32 + colA) ^ xv));
            }
            uint32_t b[4][2];
            #pragma unroll
            for (int np = 0; np < 2; np++) {
                uint32_t br = (uint32_t)(rowB + np * 16) * 128;
                uint32_t xv = (br >> 3) & 0x70;
                uint32_t r0, r1, r2, r3;
                ldsm4(r0, r1, r2, r3, Bs + br + ((kk * 32 + colB) ^ xv));
                b[np * 2][0] = r0; b[np * 2][1] = r1;
                b[np * 2 + 1][0] = r2; b[np * 2 + 1][1] = r3;
            }
            #pragma unroll
            for (int m = 0; m < 4; m++)
                #pragma unroll
                for (int n = 0; n < 4; n++)
                    mma16816(cAcc[m][n], a[m], b[n]);
        }

        s++; if (s == GS) s = 0;
    }

    // epilogue: registers -> global
    int r0 = lane >> 2, c0 = (lane & 3) * 2;
    #pragma unroll
    for (int m = 0; m < 4; m++) {
        #pragma unroll
        for (int n = 0; n < 4; n++) {
            int gnc = nBase + wn * 32 + n * 8 + c0;
            #pragma unroll
            for (int h = 0; h < 2; h++) {
                int gm = mBase + wm * 64 + m * 16 + r0 + h * 8;
                float v0 = cAcc[m][n][h * 2 + 0];
                float v1 = cAcc[m][n][h * 2 + 1];
                if (epi == 0) {
                    __half2 hv = __floats2half2_rn(v0, v1);
                    *(__half2*)(outH + (size_t)gm * ldo + gnc) = hv;
                } else if (epi == 1) {
                    float o0 = 0.f, o1 = 0.f;
                    if (gnc < Nvalid) {
                        float t = v0 + bias[gnc];
                        o0 = 0.5f * t * (1.f + erff(t * 0.70710678118654752f));
                    }
                    if (gnc + 1 < Nvalid) {
                        float t = v1 + bias[gnc + 1];
                        o1 = 0.5f * t * (1.f + erff(t * 0.70710678118654752f));
                    }
                    *(__half2*)(outH + (size_t)gm * ldo + gnc) = __floats2half2_rn(o0, o1);
                } else {
                    if (gm < Mvalid) {
                        if (gnc < Nvalid)
                            outF[(size_t)gm * Nvalid + gnc] =
                                v0 + bias[gnc] + resid[(size_t)gm * Nvalid + gnc];
                        if (gnc + 1 < Nvalid)
                            outF[(size_t)gm * Nvalid + gnc + 1] =
                                v1 + bias[gnc + 1] + resid[(size_t)gm * Nvalid + gnc + 1];
                    }
                }
            }
        }
    }
}

// ---------------- launcher ----------------
extern "C" void kernel_launch(void* const* d_in, const int* in_sizes, int n_in,
                              void* d_out, int out_size)
{
    (void)in_sizes; (void)n_in; (void)out_size;
    const float* x   = (const float*)d_in[0];
    const float* cw  = (const float*)d_in[1];
    const float* g1  = (const float*)d_in[2];
    const float* b1  = (const float*)d_in[3];
    const float* g2  = (const float*)d_in[4];
    const float* b2  = (const float*)d_in[5];
    const float* u1w = (const float*)d_in[6];
    const float* v1w = (const float*)d_in[7];
    const float* v1b = (const float*)d_in[8];
    const float* u2w = (const float*)d_in[9];
    const float* v2w = (const float*)d_in[10];
    const float* v2b = (const float*)d_in[11];
    float* out = (float*)d_out;

    void *p_stats, *p_filt, *p_ln2h, *p_a1, *p_h1, *p_a2, *p_u1, *p_v1, *p_u2, *p_v2;
    cudaGetSymbolAddress(&p_stats, g_stats);
    cudaGetSymbolAddress(&p_filt, g_filt);
    cudaGetSymbolAddress(&p_ln2h, g_ln2h);
    cudaGetSymbolAddress(&p_a1,   g_a1);
    cudaGetSymbolAddress(&p_h1,   g_h1);
    cudaGetSymbolAddress(&p_a2,   g_a2);
    cudaGetSymbolAddress(&p_u1,   g_u1h);
    cudaGetSymbolAddress(&p_v1,   g_v1h);
    cudaGetSymbolAddress(&p_u2,   g_u2h);
    cudaGetSymbolAddress(&p_v2,   g_v2h);

    cudaFuncSetAttribute(fft_filter_kernel, cudaFuncAttributeMaxDynamicSharedMemorySize,
                         FFT_SMEM_FLOATS * 4);
    cudaFuncSetAttribute(gemm_mma, cudaFuncAttributeMaxDynamicSharedMemorySize, GEMM_SMEM);

    convert_all<<<(CVT_S4 + 255) / 256, 256>>>(u1w, v1w, u2w, v2w,
        (__half*)p_u1, (__half*)p_v1, (__half*)p_u2, (__half*)p_v2);

    ln1_stats<<<MTOK, 128>>>(x, (float*)p_stats);

    fft_filter_kernel<<<dim3(CDIM / FCH, BATCH), 256, FFT_SMEM_FLOATS * 4>>>(
        x, (const float*)p_stats, g1, b1, cw, (float*)p_filt);

    ln2_kernel<<<MTOK, 128>>>((const float*)p_filt, g2, b2, (__half*)p_ln2h);

    // z1 = ln2 @ u1^T   (M x 512pad), K: 15 tiles (cols 960..1023 all-zero, skipped)
    gemm_mma<<<dim3(RPAD / 128, MPAD / 128), 256, GEMM_SMEM>>>(
        (const __half*)p_ln2h, CPAD, (const __half*)p_u1, CPAD,
        (__half*)p_a1, RPAD, nullptr, nullptr, nullptr, RANK, 15, 0, MTOK);

    // h = gelu(z1 @ v1^T + b)  (M x 1920pad), K = 512pad
    gemm_mma<<<dim3(HPAD / 128, MPAD / 128), 256, GEMM_SMEM>>>(
        (const __half*)p_a1, RPAD, (const __half*)p_v1, RPAD,
        (__half*)p_h1, HPAD, nullptr, v1b, nullptr, HID, RPAD / 64, 1, MTOK);

    // z2 = h @ u2^T   (M x 512pad), K: 29 tiles (cols 1856..1919 all-zero, skipped)
    gemm_mma<<<dim3(RPAD / 128, MPAD / 128), 256, GEMM_SMEM>>>(
        (const __half*)p_h1, HPAD, (const __half*)p_u2, HPAD,
        (__half*)p_a2, RPAD, nullptr, nullptr, nullptr, RANK, 29, 0, MTOK);

    // out = z2 @ v2^T + b + x  (M x 1024pad -> 900 valid), K = 512pad
    gemm_mma<<<dim3(CPAD / 128, MPAD / 128), 256, GEMM_SMEM>>>(
        (const __half*)p_a2, RPAD, (const __half*)p_v2, RPAD,
        nullptr, CDIM, out, v2b, x, CDIM, RPAD / 64, 2, MTOK);
}

// round 16
// speedup vs baseline: 1.2832x; 1.0153x over previous
#include <cuda_runtime.h>
#include <cuda_fp16.h>
#include <cstdint>

// ---------------- problem constants ----------------
#define BATCH   64
#define NSPAT   891            // 9*11*9
#define CDIM    900
#define MTOK    (BATCH*NSPAT)  // 57024
#define MPAD    57088          // 446 * 128
#define RANK    450
#define HID     1800
#define RPAD    512            // 4  * 128
#define HPAD    1920           // 15 * 128
#define CPAD    1024           // 8  * 128

// ---------------- scratch (device globals; zero-initialized at load) ------
__device__ float  g_stats [(size_t)MTOK * 2];        // LN1 per-token mean, inv
__device__ float  g_stats2[(size_t)MTOK * 2];        // LN2 per-token mean, inv
__device__ float  g_c0[RPAD];                        // u1 @ beta2
__device__ float  g_c1[RPAD];                        // u1 @ gamma2
__device__ __half g_filth[(size_t)MPAD * CPAD];      // fp16 filt (pad = 0)
__device__ __half g_a1  [(size_t)MPAD * RPAD];
__device__ __half g_h1  [(size_t)MPAD * HPAD];
__device__ __half g_a2  [(size_t)MPAD * RPAD];
__device__ __half g_u1h [(size_t)RPAD * CPAD];       // u1 ⊙ gamma2, padded
__device__ __half g_v1h [(size_t)HPAD * RPAD];
__device__ __half g_u2h [(size_t)RPAD * HPAD];
__device__ __half g_v2h [(size_t)CPAD * RPAD];

// ---------------- PTX helpers ----------------
__device__ __forceinline__ uint32_t smem_u32(const void* p) {
    uint32_t a;
    asm("{ .reg .u64 t; cvta.to.shared.u64 t, %1; cvt.u32.u64 %0, t; }" : "=r"(a) : "l"(p));
    return a;
}
#define SWZ128(off) ((off) ^ (((off) >> 3) & 0x70))

__device__ __forceinline__ void cp_async16(uint32_t dst, const void* src) {
    asm volatile("cp.async.cg.shared.global [%0], [%1], 16;" :: "r"(dst), "l"(src) : "memory");
}
__device__ __forceinline__ void cp_commit() {
    asm volatile("cp.async.commit_group;" ::: "memory");
}
__device__ __forceinline__ void cp_wait1() {
    asm volatile("cp.async.wait_group 1;" ::: "memory");
}
__device__ __forceinline__ void ldsm4(uint32_t& r0, uint32_t& r1, uint32_t& r2, uint32_t& r3,
                                      uint32_t addr) {
    asm volatile("ldmatrix.sync.aligned.m8n8.x4.shared.b16 {%0,%1,%2,%3}, [%4];"
                 : "=r"(r0), "=r"(r1), "=r"(r2), "=r"(r3) : "r"(addr));
}
__device__ __forceinline__ void mma16816(float* c, const uint32_t* a, const uint32_t* b) {
    asm volatile(
        "mma.sync.aligned.m16n8k16.row.col.f32.f16.f16.f32 "
        "{%0,%1,%2,%3}, {%4,%5,%6,%7}, {%8,%9}, {%0,%1,%2,%3};"
        : "+f"(c[0]), "+f"(c[1]), "+f"(c[2]), "+f"(c[3])
        : "r"(a[0]), "r"(a[1]), "r"(a[2]), "r"(a[3]), "r"(b[0]), "r"(b[1]));
}

// ---------------- fused weight convert + pad (u1 folded with gamma2) ------
#define CVT_S1 (RPAD*CPAD)
#define CVT_S2 (CVT_S1 + HPAD*RPAD)
#define CVT_S3 (CVT_S2 + RPAD*HPAD)
#define CVT_S4 (CVT_S3 + CPAD*RPAD)

__global__ void convert_all(const float* __restrict__ u1, const float* __restrict__ v1,
                            const float* __restrict__ u2, const float* __restrict__ v2,
                            const float* __restrict__ g2,
                            __half* __restrict__ du1, __half* __restrict__ dv1,
                            __half* __restrict__ du2, __half* __restrict__ dv2)
{
    int i = blockIdx.x * blockDim.x + threadIdx.x;
    if (i >= CVT_S4) return;
    if (i < CVT_S1) {
        int n = i / CPAD, k = i - n * CPAD;
        float v = (n < RANK && k < CDIM) ? u1[n * CDIM + k] * g2[k] : 0.f;
        du1[i] = __float2half(v);
    } else if (i < CVT_S2) {
        int j = i - CVT_S1; int n = j / RPAD, k = j - n * RPAD;
        float v = (n < HID && k < RANK) ? v1[n * RANK + k] : 0.f;
        dv1[j] = __float2half(v);
    } else if (i < CVT_S3) {
        int j = i - CVT_S2; int n = j / HPAD, k = j - n * HPAD;
        float v = (n < RANK && k < HID) ? u2[n * HID + k] : 0.f;
        du2[j] = __float2half(v);
    } else {
        int j = i - CVT_S3; int n = j / RPAD, k = j - n * RPAD;
        float v = (n < CDIM && k < RANK) ? v2[n * RANK + k] : 0.f;
        dv2[j] = __float2half(v);
    }
}

// ---------------- block reduce (sum, sumsq / two sums) ----------------
__device__ __forceinline__ void blockReduce2(float& a, float& b)
{
    #pragma unroll
    for (int o = 16; o > 0; o >>= 1) {
        a += __shfl_down_sync(0xffffffffu, a, o);
        b += __shfl_down_sync(0xffffffffu, b, o);
    }
    __shared__ float sa[4], sb[4];
    int w = threadIdx.x >> 5, l = threadIdx.x & 31;
    if (l == 0) { sa[w] = a; sb[w] = b; }
    __syncthreads();
    if (threadIdx.x == 0) {
        float ta = 0.f, tb = 0.f;
        #pragma unroll
        for (int i = 0; i < 4; i++) { ta += sa[i]; tb += sb[i]; }
        sa[0] = ta; sb[0] = tb;
    }
    __syncthreads();
    a = sa[0]; b = sb[0];
}

// ---------------- c0 = u1 @ beta2, c1 = u1 @ gamma2 (RPAD rows) -----------
__global__ void __launch_bounds__(128) lnc_kernel(const float* __restrict__ u1,
                                                  const float* __restrict__ g2,
                                                  const float* __restrict__ b2,
                                                  float* __restrict__ c0,
                                                  float* __restrict__ c1)
{
    int j = blockIdx.x;
    float s0 = 0.f, s1 = 0.f;
    if (j < RANK) {
        const float* row = u1 + (size_t)j * CDIM;
        for (int c = threadIdx.x; c < CDIM; c += 128) {
            float u = row[c];
            s0 += u * b2[c];
            s1 += u * g2[c];
        }
    }
    blockReduce2(s0, s1);
    if (threadIdx.x == 0) { c0[j] = s0; c1[j] = s1; }
}

// ---------------- LN1 stats only ----------------
__global__ void __launch_bounds__(128) ln1_stats(const float* __restrict__ x,
                                                 float* __restrict__ stats)
{
    size_t row = blockIdx.x;
    const float* xr = x + row * CDIM;
    float s = 0.f, ss = 0.f;
    #pragma unroll
    for (int i = 0; i < 8; i++) {
        int c = threadIdx.x + i * 128;
        float v = (c < CDIM) ? xr[c] : 0.f;
        s += v; ss += v * v;
    }
    blockReduce2(s, ss);
    if (threadIdx.x == 0) {
        float mean = s * (1.f / CDIM);
        float var  = ss * (1.f / CDIM) - mean * mean;
        stats[row * 2]     = mean;
        stats[row * 2 + 1] = rsqrtf(var + 1e-5f);
    }
}

// ---------------- LN2 stats from fp16 filt ----------------
__global__ void __launch_bounds__(128) ln2_stats(const __half* __restrict__ in,
                                                 float* __restrict__ stats)
{
    size_t row = blockIdx.x;
    const __half* xr = in + row * CPAD;
    float s = 0.f, ss = 0.f;
    #pragma unroll
    for (int i = 0; i < 8; i++) {
        int c = threadIdx.x + i * 128;
        float v = (c < CDIM) ? __half2float(xr[c]) : 0.f;
        s += v; ss += v * v;
    }
    blockReduce2(s, ss);
    if (threadIdx.x == 0) {
        float mean = s * (1.f / CDIM);
        float var  = ss * (1.f / CDIM) - mean * mean;
        stats[row * 2]     = mean;
        stats[row * 2 + 1] = rsqrtf(var + 1e-5f);
    }
}

// ---------------- fused LN1-normalize + 3D spectral filter (sym DFT) ------
// Output written directly as fp16 into g_filth (row stride CPAD).
#define FCH 12
#define FFT_SMEM_FLOATS (891*FCH + 2*495*FCH + 2*(45+121+81) + 2*891 + 2*FCH)

__global__ void __launch_bounds__(256) fft_filter_kernel(const float* __restrict__ xin,
                                                         const float* __restrict__ stats,
                                                         const float* __restrict__ g1,
                                                         const float* __restrict__ b1,
                                                         const float* __restrict__ cw,
                                                         __half* __restrict__ yout)
{
    extern __shared__ float sm[];
    float* sR  = sm;
    float* sCr = sR  + 891 * FCH;
    float* sCi = sCr + 495 * FCH;
    float* cD  = sCi + 495 * FCH;
    float* sD  = cD + 45;
    float* cWt = sD + 45;
    float* sWt = cWt + 121;
    float* cHt = sWt + 121;
    float* sHt = cHt + 81;
    float* sSt = sHt + 81;
    float* sG  = sSt + 2 * 891;
    float* sB  = sG + FCH;

    int tid = threadIdx.x;
    int b   = blockIdx.y;
    int c0  = blockIdx.x * FCH;

    for (int i = tid; i < 45; i += 256) {
        int kd = i / 9, d = i % 9; float s, c;
        sincospif(2.f * (float)(kd * d) / 9.f, &s, &c);
        cD[i] = c; sD[i] = s;
    }
    for (int i = tid; i < 121; i += 256) {
        int j = i / 11, k = i % 11; float s, c;
        sincospif(2.f * (float)(j * k) / 11.f, &s, &c);
        cWt[i] = c; sWt[i] = s;
    }
    for (int i = tid; i < 81; i += 256) {
        int j = i / 9, k = i % 9; float s, c;
        sincospif(2.f * (float)(j * k) / 9.f, &s, &c);
        cHt[i] = c; sHt[i] = s;
    }
    for (int i = tid; i < 2 * 891; i += 256)
        sSt[i] = stats[(size_t)b * NSPAT * 2 + i];
    if (tid < FCH) { sG[tid] = g1[c0 + tid]; sB[tid] = b1[c0 + tid]; }
    __syncthreads();

    const float* src = xin + ((size_t)b * NSPAT) * CDIM + c0;
    for (int i = tid; i < 891 * FCH; i += 256) {
        int n = i / FCH, cc = i - n * FCH;
        float raw = src[(size_t)n * CDIM + cc];
        sR[i] = (raw - sSt[n * 2]) * sSt[n * 2 + 1] * sG[cc] + sB[cc];
    }
    __syncthreads();

    // S1: rfft along D (real 9 -> 5 complex), folded
    for (int l = tid; l < 99 * FCH; l += 256) {
        int hw = l / FCH, cc = l - hw * FCH;
        float xr[9];
        #pragma unroll
        for (int d = 0; d < 9; d++) xr[d] = sR[(hw * 9 + d) * FCH + cc];
        float sp[4], smd[4];
        #pragma unroll
        for (int i = 0; i < 4; i++) { sp[i] = xr[i + 1] + xr[8 - i]; smd[i] = xr[i + 1] - xr[8 - i]; }
        #pragma unroll
        for (int kd = 0; kd < 5; kd++) {
            float re = xr[0], im = 0.f;
            #pragma unroll
            for (int i = 0; i < 4; i++) {
                re += sp[i]  * cD[kd * 9 + i + 1];
                im -= smd[i] * sD[kd * 9 + i + 1];
            }
            sCr[(hw * 5 + kd) * FCH + cc] = re;
            sCi[(hw * 5 + kd) * FCH + cc] = im;
        }
    }
    __syncthreads();

    // S2: forward FFT along W (11 pt), double-folded
    for (int l = tid; l < 9 * 5 * FCH; l += 256) {
        int h = l / (5 * FCH); int r = l - h * (5 * FCH); int kd = r / FCH, cc = r - kd * FCH;
        float ar[11], ai[11];
        #pragma unroll
        for (int w = 0; w < 11; w++) {
            int p = ((h * 11 + w) * 5 + kd) * FCH + cc;
            ar[w] = sCr[p]; ai[w] = sCi[p];
        }
        float arp[5], arm[5], aip[5], aim[5];
        #pragma unroll
        for (int k = 0; k < 5; k++) {
            arp[k] = ar[k + 1] + ar[10 - k]; arm[k] = ar[k + 1] - ar[10 - k];
            aip[k] = ai[k + 1] + ai[10 - k]; aim[k] = ai[k + 1] - ai[10 - k];
        }
        {
            float re0 = ar[0] + arp[0] + arp[1] + arp[2] + arp[3] + arp[4];
            float im0 = ai[0] + aip[0] + aip[1] + aip[2] + aip[3] + aip[4];
            int p = ((h * 11 + 0) * 5 + kd) * FCH + cc;
            sCr[p] = re0; sCi[p] = im0;
        }
        #pragma unroll
        for (int jp = 1; jp <= 5; jp++) {
            float A = ar[0], C = ai[0], B = 0.f, D = 0.f;
            #pragma unroll
            for (int k = 1; k <= 5; k++) {
                float c = cWt[jp * 11 + k], s = sWt[jp * 11 + k];
                A += arp[k - 1] * c;  D += arm[k - 1] * s;
                C += aip[k - 1] * c;  B += aim[k - 1] * s;
            }
            int p1 = ((h * 11 + jp) * 5 + kd) * FCH + cc;
            int p2 = ((h * 11 + (11 - jp)) * 5 + kd) * FCH + cc;
            sCr[p1] = A + B; sCi[p1] = C - D;
            sCr[p2] = A - B; sCi[p2] = C + D;
        }
    }
    __syncthreads();

    // S3: forward FFT along H (9 pt), double-folded
    for (int l = tid; l < 11 * 5 * FCH; l += 256) {
        int w = l / (5 * FCH); int r = l - w * (5 * FCH); int kd = r / FCH, cc = r - kd * FCH;
        float ar[9], ai[9];
        #pragma unroll
        for (int h = 0; h < 9; h++) {
            int p = ((h * 11 + w) * 5 + kd) * FCH + cc;
            ar[h] = sCr[p]; ai[h] = sCi[p];
        }
        float arp[4], arm[4], aip[4], aim[4];
        #pragma unroll
        for (int k = 0; k < 4; k++) {
            arp[k] = ar[k + 1] + ar[8 - k]; arm[k] = ar[k + 1] - ar[8 - k];
            aip[k] = ai[k + 1] + ai[8 - k]; aim[k] = ai[k + 1] - ai[8 - k];
        }
        {
            float re0 = ar[0] + arp[0] + arp[1] + arp[2] + arp[3];
            float im0 = ai[0] + aip[0] + aip[1] + aip[2] + aip[3];
            int p = ((0 * 11 + w) * 5 + kd) * FCH + cc;
            sCr[p] = re0; sCi[p] = im0;
        }
        #pragma unroll
        for (int jp = 1; jp <= 4; jp++) {
            float A = ar[0], C = ai[0], B = 0.f, D = 0.f;
            #pragma unroll
            for (int k = 1; k <= 4; k++) {
                float c = cHt[jp * 9 + k], s = sHt[jp * 9 + k];
                A += arp[k - 1] * c;  D += arm[k - 1] * s;
                C += aip[k - 1] * c;  B += aim[k - 1] * s;
            }
            int p1 = ((jp * 11 + w) * 5 + kd) * FCH + cc;
            int p2 = (((9 - jp) * 11 + w) * 5 + kd) * FCH + cc;
            sCr[p1] = A + B; sCi[p1] = C - D;
            sCr[p2] = A - B; sCi[p2] = C + D;
        }
    }
    __syncthreads();

    // weight multiply (ortho 1/891 folded in)
    {
        const float scl = 1.f / 891.f;
        for (int i = tid; i < 495 * FCH; i += 256) {
            int f = i / FCH, cc = i - f * FCH;
            size_t wi = ((size_t)f * CDIM + c0 + cc) * 2;
            float wr = cw[wi] * scl, wim = cw[wi + 1] * scl;
            float xr = sCr[i], xi = sCi[i];
            sCr[i] = xr * wr - xi * wim;
            sCi[i] = xr * wim + xi * wr;
        }
    }
    __syncthreads();

    // inverse FFT along H
    for (int l = tid; l < 11 * 5 * FCH; l += 256) {
        int w = l / (5 * FCH); int r = l - w * (5 * FCH); int kd = r / FCH, cc = r - kd * FCH;
        float ar[9], ai[9];
        #pragma unroll
        for (int h = 0; h < 9; h++) {
            int p = ((h * 11 + w) * 5 + kd) * FCH + cc;
            ar[h] = sCr[p]; ai[h] = sCi[p];
        }
        float arp[4], arm[4], aip[4], aim[4];
        #pragma unroll
        for (int k = 0; k < 4; k++) {
            arp[k] = ar[k + 1] + ar[8 - k]; arm[k] = ar[k + 1] - ar[8 - k];
            aip[k] = ai[k + 1] + ai[8 - k]; aim[k] = ai[k + 1] - ai[8 - k];
        }
        {
            float re0 = ar[0] + arp[0] + arp[1] + arp[2] + arp[3];
            float im0 = ai[0] + aip[0] + aip[1] + aip[2] + aip[3];
            int p = ((0 * 11 + w) * 5 + kd) * FCH + cc;
            sCr[p] = re0; sCi[p] = im0;
        }
        #pragma unroll
        for (int jp = 1; jp <= 4; jp++) {
            float A = ar[0], C = ai[0], B = 0.f, D = 0.f;
            #pragma unroll
            for (int k = 1; k <= 4; k++) {
                float c = cHt[jp * 9 + k], s = sHt[jp * 9 + k];
                A += arp[k - 1] * c;  D += arm[k - 1] * s;
                C += aip[k - 1] * c;  B += aim[k - 1] * s;
            }
            int p1 = ((jp * 11 + w) * 5 + kd) * FCH + cc;
            int p2 = (((9 - jp) * 11 + w) * 5 + kd) * FCH + cc;
            sCr[p1] = A - B; sCi[p1] = C + D;
            sCr[p2] = A + B; sCi[p2] = C - D;
        }
    }
    __syncthreads();

    // inverse FFT along W
    for (int l = tid; l < 9 * 5 * FCH; l += 256) {
        int h = l / (5 * FCH); int r = l - h * (5 * FCH); int kd = r / FCH, cc = r - kd * FCH;
        float ar[11], ai[11];
        #pragma unroll
        for (int w = 0; w < 11; w++) {
            int p = ((h * 11 + w) * 5 + kd) * FCH + cc;
            ar[w] = sCr[p]; ai[w] = sCi[p];
        }
        float arp[5], arm[5], aip[5], aim[5];
        #pragma unroll
        for (int k = 0; k < 5; k++) {
            arp[k] = ar[k + 1] + ar[10 - k]; arm[k] = ar[k + 1] - ar[10 - k];
            aip[k] = ai[k + 1] + ai[10 - k]; aim[k] = ai[k + 1] - ai[10 - k];
        }
        {
            float re0 = ar[0] + arp[0] + arp[1] + arp[2] + arp[3] + arp[4];
            float im0 = ai[0] + aip[0] + aip[1] + aip[2] + aip[3] + aip[4];
            int p = ((h * 11 + 0) * 5 + kd) * FCH + cc;
            sCr[p] = re0; sCi[p] = im0;
        }
        #pragma unroll
        for (int jp = 1; jp <= 5; jp++) {
            float A = ar[0], C = ai[0], B = 0.f, D = 0.f;
            #pragma unroll
            for (int k = 1; k <= 5; k++) {
                float c = cWt[jp * 11 + k], s = sWt[jp * 11 + k];
                A += arp[k - 1] * c;  D += arm[k - 1] * s;
                C += aip[k - 1] * c;  B += aim[k - 1] * s;
            }
            int p1 = ((h * 11 + jp) * 5 + kd) * FCH + cc;
            int p2 = ((h * 11 + (11 - jp)) * 5 + kd) * FCH + cc;
            sCr[p1] = A - B; sCi[p1] = C + D;
            sCr[p2] = A + B; sCi[p2] = C - D;
        }
    }
    __syncthreads();

    // irfft along D -> global fp16 (row stride CPAD)
    __half* dst = yout + ((size_t)b * NSPAT) * CPAD + c0;
    for (int l = tid; l < 99 * FCH; l += 256) {
        int hw = l / FCH, cc = l - hw * FCH;
        float Xr[5], Xi[5];
        #pragma unroll
        for (int kd = 0; kd < 5; kd++) {
            int p = (hw * 5 + kd) * FCH + cc;
            Xr[kd] = sCr[p]; Xi[kd] = sCi[p];
        }
        float t0 = Xr[0];
        dst[(size_t)(hw * 9 + 0) * CPAD + cc] =
            __float2half(t0 + 2.f * (Xr[1] + Xr[2] + Xr[3] + Xr[4]));
        #pragma unroll
        for (int dp = 1; dp <= 4; dp++) {
            float P = 0.f, Q = 0.f;
            #pragma unroll
            for (int k = 1; k <= 4; k++) {
                P += Xr[k] * cD[k * 9 + dp];
                Q += Xi[k] * sD[k * 9 + dp];
            }
            dst[(size_t)(hw * 9 + dp) * CPAD + cc]       = __float2half(t0 + 2.f * (P - Q));
            dst[(size_t)(hw * 9 + (9 - dp)) * CPAD + cc] = __float2half(t0 + 2.f * (P + Q));
        }
    }
}

// ---------------- mma.sync GEMM (R13 config) ------------------------------
// epi 0: half | epi 1: +bias, gelu, half | epi 2: +bias +residual, float |
// epi 3: LN2-folded: out = inv*acc + c0 - inv*mean*c1, half
#define GS      3
#define STAGEB  32768
#define GEMM_SMEM (GS*STAGEB)

__device__ __forceinline__ void load_stage(
    const __half* __restrict__ A, int lda,
    const __half* __restrict__ B, int ldb,
    int mBase, int nBase, uint32_t data0, int sn, int kt, int tid)
{
    uint32_t sbase = data0 + sn * STAGEB;
    #pragma unroll
    for (int j = 0; j < 8; j++) {
        int ci = tid + j * 256;
        int v  = ci & 1023;
        int row = v >> 3;
        int cb  = (v & 7) << 4;
        const __half* g;
        uint32_t dst;
        if (ci < 1024) {
            g   = A + (size_t)(mBase + row) * lda + kt * 64 + (cb >> 1);
            dst = sbase + SWZ128(row * 128 + cb);
        } else {
            g   = B + (size_t)(nBase + row) * ldb + kt * 64 + (cb >> 1);
            dst = sbase + 16384 + SWZ128(row * 128 + cb);
        }
        cp_async16(dst, g);
    }
}

__global__ void __launch_bounds__(256, 2) gemm_mma(
    const __half* __restrict__ A, int lda,
    const __half* __restrict__ B, int ldb,
    __half* outH, int ldo,
    float* outF,
    const float* __restrict__ bias,       // epi1/2: bias; epi3: c0
    const float* __restrict__ resid,      // epi2: residual
    const float* __restrict__ c1v,        // epi3: c1
    const float* __restrict__ stats2,     // epi3: per-row (mean, inv)
    int Nvalid, int KT, int epi, int Mvalid)
{
    extern __shared__ __align__(1024) char smem[];
    uint32_t data0 = smem_u32(smem);

    int tid   = threadIdx.x;
    int lane  = tid & 31;
    int warp  = tid >> 5;
    int wm    = warp >> 2;
    int wn    = warp & 3;
    int nBase = blockIdx.x * 128;
    int mBase = blockIdx.y * 128;

    int mi  = lane >> 3, rin = lane & 7;
    int rowA = wm * 64 + (mi & 1) * 8 + rin;
    int colA = (mi >> 1) * 16;
    int rowB = wn * 32 + (mi >> 1) * 8 + rin;
    int colB = (mi & 1) * 16;

    float cAcc[4][4][4];
    #pragma unroll
    for (int m = 0; m < 4; m++)
        #pragma unroll
        for (int n = 0; n < 4; n++)
            #pragma unroll
            for (int r = 0; r < 4; r++) cAcc[m][n][r] = 0.f;

    load_stage(A, lda, B, ldb, mBase, nBase, data0, 0, 0, tid);
    cp_commit();
    load_stage(A, lda, B, ldb, mBase, nBase, data0, 1, 1, tid);
    cp_commit();

    int s = 0;
    for (int k = 0; k < KT; k++) {
        cp_wait1();
        __syncthreads();

        int kn = k + 2;
        if (kn < KT) {
            int sn = s + 2; if (sn >= GS) sn -= GS;
            load_stage(A, lda, B, ldb, mBase, nBase, data0, sn, kn, tid);
        }
        cp_commit();

        uint32_t As = data0 + s * STAGEB;
        uint32_t Bs = As + 16384;
        #pragma unroll
        for (int kk = 0; kk < 4; kk++) {
            uint32_t a[4][4];
            #pragma unroll
            for (int m = 0; m < 4; m++) {
                uint32_t br = (uint32_t)(rowA + m * 16) * 128;
                uint32_t xv = (br >> 3) & 0x70;
                ldsm4(a[m][0], a[m][1], a[m][2], a[m][3],
                      As + br + ((kk * 32 + colA) ^ xv));
            }
            uint32_t b[4][2];
            #pragma unroll
            for (int np = 0; np < 2; np++) {
                uint32_t br = (uint32_t)(rowB + np * 16) * 128;
                uint32_t xv = (br >> 3) & 0x70;
                uint32_t r0, r1, r2, r3;
                ldsm4(r0, r1, r2, r3, Bs + br + ((kk * 32 + colB) ^ xv));
                b[np * 2][0] = r0; b[np * 2][1] = r1;
                b[np * 2 + 1][0] = r2; b[np * 2 + 1][1] = r3;
            }
            #pragma unroll
            for (int m = 0; m < 4; m++)
                #pragma unroll
                for (int n = 0; n < 4; n++)
                    mma16816(cAcc[m][n], a[m], b[n]);
        }

        s++; if (s == GS) s = 0;
    }

    // epilogue
    int r0 = lane >> 2, c0c = (lane & 3) * 2;
    #pragma unroll
    for (int m = 0; m < 4; m++) {
        #pragma unroll
        for (int n = 0; n < 4; n++) {
            int gnc = nBase + wn * 32 + n * 8 + c0c;
            #pragma unroll
            for (int h = 0; h < 2; h++) {
                int gm = mBase + wm * 64 + m * 16 + r0 + h * 8;
                float v0 = cAcc[m][n][h * 2 + 0];
                float v1 = cAcc[m][n][h * 2 + 1];
                if (epi == 0) {
                    *(__half2*)(outH + (size_t)gm * ldo + gnc) = __floats2half2_rn(v0, v1);
                } else if (epi == 1) {
                    float o0 = 0.f, o1 = 0.f;
                    if (gnc < Nvalid) {
                        float t = v0 + bias[gnc];
                        o0 = 0.5f * t * (1.f + erff(t * 0.70710678118654752f));
                    }
                    if (gnc + 1 < Nvalid) {
                        float t = v1 + bias[gnc + 1];
                        o1 = 0.5f * t * (1.f + erff(t * 0.70710678118654752f));
                    }
                    *(__half2*)(outH + (size_t)gm * ldo + gnc) = __floats2half2_rn(o0, o1);
                } else if (epi == 3) {
                    float mean = stats2[(size_t)gm * 2];
                    float inv  = stats2[(size_t)gm * 2 + 1];
                    float sm_  = inv * mean;
                    float o0 = inv * v0 + bias[gnc]     - sm_ * c1v[gnc];
                    float o1 = inv * v1 + bias[gnc + 1] - sm_ * c1v[gnc + 1];
                    *(__half2*)(outH + (size_t)gm * ldo + gnc) = __floats2half2_rn(o0, o1);
                } else {
                    if (gm < Mvalid) {
                        if (gnc < Nvalid)
                            outF[(size_t)gm * Nvalid + gnc] =
                                v0 + bias[gnc] + resid[(size_t)gm * Nvalid + gnc];
                        if (gnc + 1 < Nvalid)
                            outF[(size_t)gm * Nvalid + gnc + 1] =
                                v1 + bias[gnc + 1] + resid[(size_t)gm * Nvalid + gnc + 1];
                    }
                }
            }
        }
    }
}

// ---------------- launcher ----------------
extern "C" void kernel_launch(void* const* d_in, const int* in_sizes, int n_in,
                              void* d_out, int out_size)
{
    (void)in_sizes; (void)n_in; (void)out_size;
    const float* x   = (const float*)d_in[0];
    const float* cw  = (const float*)d_in[1];
    const float* g1  = (const float*)d_in[2];
    const float* b1  = (const float*)d_in[3];
    const float* g2  = (const float*)d_in[4];
    const float* b2  = (const float*)d_in[5];
    const float* u1w = (const float*)d_in[6];
    const float* v1w = (const float*)d_in[7];
    const float* v1b = (const float*)d_in[8];
    const float* u2w = (const float*)d_in[9];
    const float* v2w = (const float*)d_in[10];
    const float* v2b = (const float*)d_in[11];
    float* out = (float*)d_out;

    void *p_st, *p_st2, *p_c0, *p_c1, *p_fh, *p_a1, *p_h1, *p_a2, *p_u1, *p_v1, *p_u2, *p_v2;
    cudaGetSymbolAddress(&p_st,  g_stats);
    cudaGetSymbolAddress(&p_st2, g_stats2);
    cudaGetSymbolAddress(&p_c0,  g_c0);
    cudaGetSymbolAddress(&p_c1,  g_c1);
    cudaGetSymbolAddress(&p_fh,  g_filth);
    cudaGetSymbolAddress(&p_a1,  g_a1);
    cudaGetSymbolAddress(&p_h1,  g_h1);
    cudaGetSymbolAddress(&p_a2,  g_a2);
    cudaGetSymbolAddress(&p_u1,  g_u1h);
    cudaGetSymbolAddress(&p_v1,  g_v1h);
    cudaGetSymbolAddress(&p_u2,  g_u2h);
    cudaGetSymbolAddress(&p_v2,  g_v2h);

    cudaFuncSetAttribute(fft_filter_kernel, cudaFuncAttributeMaxDynamicSharedMemorySize,
                         FFT_SMEM_FLOATS * 4);
    cudaFuncSetAttribute(gemm_mma, cudaFuncAttributeMaxDynamicSharedMemorySize, GEMM_SMEM);

    convert_all<<<(CVT_S4 + 255) / 256, 256>>>(u1w, v1w, u2w, v2w, g2,
        (__half*)p_u1, (__half*)p_v1, (__half*)p_u2, (__half*)p_v2);

    lnc_kernel<<<RPAD, 128>>>(u1w, g2, b2, (float*)p_c0, (float*)p_c1);

    ln1_stats<<<MTOK, 128>>>(x, (float*)p_st);

    fft_filter_kernel<<<dim3(CDIM / FCH, BATCH), 256, FFT_SMEM_FLOATS * 4>>>(
        x, (const float*)p_st, g1, b1, cw, (__half*)p_fh);

    ln2_stats<<<MTOK, 128>>>((const __half*)p_fh, (float*)p_st2);

    // z1 = LN2-folded: inv*(filt @ (u1.g2)^T) + c0 - inv*mean*c1   (epi 3)
    gemm_mma<<<dim3(RPAD / 128, MPAD / 128), 256, GEMM_SMEM>>>(
        (const __half*)p_fh, CPAD, (const __half*)p_u1, CPAD,
        (__half*)p_a1, RPAD, nullptr, (const float*)p_c0, nullptr,
        (const float*)p_c1, (const float*)p_st2, RANK, 15, 3, MTOK);

    // h = gelu(z1 @ v1^T + b)
    gemm_mma<<<dim3(HPAD / 128, MPAD / 128), 256, GEMM_SMEM>>>(
        (const __half*)p_a1, RPAD, (const __half*)p_v1, RPAD,
        (__half*)p_h1, HPAD, nullptr, v1b, nullptr, nullptr, nullptr,
        HID, RPAD / 64, 1, MTOK);

    // z2 = h @ u2^T  (29 K-tiles)
    gemm_mma<<<dim3(RPAD / 128, MPAD / 128), 256, GEMM_SMEM>>>(
        (const __half*)p_h1, HPAD, (const __half*)p_u2, HPAD,
        (__half*)p_a2, RPAD, nullptr, nullptr, nullptr, nullptr, nullptr,
        RANK, 29, 0, MTOK);

    // out = z2 @ v2^T + b + x
    gemm_mma<<<dim3(CPAD / 128, MPAD / 128), 256, GEMM_SMEM>>>(
        (const __half*)p_a2, RPAD, (const __half*)p_v2, RPAD,
        nullptr, CDIM, out, v2b, x, nullptr, nullptr,
        CDIM, RPAD / 64, 2, MTOK);
}

// round 17
// speedup vs baseline: 1.3740x; 1.0707x over previous
#include <cuda_runtime.h>
#include <cuda_fp16.h>
#include <cstdint>

// ---------------- problem constants ----------------
#define BATCH   64
#define NSPAT   891            // 9*11*9
#define CDIM    900
#define MTOK    (BATCH*NSPAT)  // 57024
#define MPAD    57088          // 446 * 128
#define RANK    450
#define HID     1800
#define RPAD    512            // 4  * 128
#define HPAD    1920           // 15 * 128
#define CPAD    1024           // 8  * 128

// ---------------- scratch (device globals; zero-initialized at load) ------
__device__ float  g_stats [(size_t)MTOK * 2];        // LN1 per-token mean, inv
__device__ float  g_stats2[(size_t)MTOK * 2];        // LN2 per-token mean, inv
__device__ float  g_c0[RPAD];                        // u1 @ beta2
__device__ float  g_c1[RPAD];                        // u1 @ gamma2
__device__ __half g_filth[(size_t)MPAD * CPAD];      // fp16 filt (pad = 0)
__device__ __half g_a1  [(size_t)MPAD * RPAD];
__device__ __half g_h1  [(size_t)MPAD * HPAD];
__device__ __half g_a2  [(size_t)MPAD * RPAD];
__device__ __half g_u1h [(size_t)RPAD * CPAD];       // u1 ⊙ gamma2, padded
__device__ __half g_v1h [(size_t)HPAD * RPAD];
__device__ __half g_u2h [(size_t)RPAD * HPAD];
__device__ __half g_v2h [(size_t)CPAD * RPAD];

// ---------------- PTX helpers ----------------
__device__ __forceinline__ uint32_t smem_u32(const void* p) {
    uint32_t a;
    asm("{ .reg .u64 t; cvta.to.shared.u64 t, %1; cvt.u32.u64 %0, t; }" : "=r"(a) : "l"(p));
    return a;
}
#define SWZ128(off) ((off) ^ (((off) >> 3) & 0x70))

__device__ __forceinline__ void cp_async16(uint32_t dst, const void* src) {
    asm volatile("cp.async.cg.shared.global [%0], [%1], 16;" :: "r"(dst), "l"(src) : "memory");
}
__device__ __forceinline__ void cp_commit() {
    asm volatile("cp.async.commit_group;" ::: "memory");
}
__device__ __forceinline__ void cp_wait1() {
    asm volatile("cp.async.wait_group 1;" ::: "memory");
}
__device__ __forceinline__ void ldsm4(uint32_t& r0, uint32_t& r1, uint32_t& r2, uint32_t& r3,
                                      uint32_t addr) {
    asm volatile("ldmatrix.sync.aligned.m8n8.x4.shared.b16 {%0,%1,%2,%3}, [%4];"
                 : "=r"(r0), "=r"(r1), "=r"(r2), "=r"(r3) : "r"(addr));
}
__device__ __forceinline__ void mma16816(float* c, const uint32_t* a, const uint32_t* b) {
    asm volatile(
        "mma.sync.aligned.m16n8k16.row.col.f32.f16.f16.f32 "
        "{%0,%1,%2,%3}, {%4,%5,%6,%7}, {%8,%9}, {%0,%1,%2,%3};"
        : "+f"(c[0]), "+f"(c[1]), "+f"(c[2]), "+f"(c[3])
        : "r"(a[0]), "r"(a[1]), "r"(a[2]), "r"(a[3]), "r"(b[0]), "r"(b[1]));
}

// ---------------- fused weight convert + pad (u1 folded with gamma2) ------
#define CVT_S1 (RPAD*CPAD)
#define CVT_S2 (CVT_S1 + HPAD*RPAD)
#define CVT_S3 (CVT_S2 + RPAD*HPAD)
#define CVT_S4 (CVT_S3 + CPAD*RPAD)

__global__ void convert_all(const float* __restrict__ u1, const float* __restrict__ v1,
                            const float* __restrict__ u2, const float* __restrict__ v2,
                            const float* __restrict__ g2,
                            __half* __restrict__ du1, __half* __restrict__ dv1,
                            __half* __restrict__ du2, __half* __restrict__ dv2)
{
    int i = blockIdx.x * blockDim.x + threadIdx.x;
    if (i >= CVT_S4) return;
    if (i < CVT_S1) {
        int n = i / CPAD, k = i - n * CPAD;
        float v = (n < RANK && k < CDIM) ? u1[n * CDIM + k] * g2[k] : 0.f;
        du1[i] = __float2half(v);
    } else if (i < CVT_S2) {
        int j = i - CVT_S1; int n = j / RPAD, k = j - n * RPAD;
        float v = (n < HID && k < RANK) ? v1[n * RANK + k] : 0.f;
        dv1[j] = __float2half(v);
    } else if (i < CVT_S3) {
        int j = i - CVT_S2; int n = j / HPAD, k = j - n * HPAD;
        float v = (n < RANK && k < HID) ? u2[n * HID + k] : 0.f;
        du2[j] = __float2half(v);
    } else {
        int j = i - CVT_S3; int n = j / RPAD, k = j - n * RPAD;
        float v = (n < CDIM && k < RANK) ? v2[n * RANK + k] : 0.f;
        dv2[j] = __float2half(v);
    }
}

// ---------------- block reduce (two sums) ----------------
__device__ __forceinline__ void blockReduce2(float& a, float& b)
{
    #pragma unroll
    for (int o = 16; o > 0; o >>= 1) {
        a += __shfl_down_sync(0xffffffffu, a, o);
        b += __shfl_down_sync(0xffffffffu, b, o);
    }
    __shared__ float sa[4], sb[4];
    int w = threadIdx.x >> 5, l = threadIdx.x & 31;
    if (l == 0) { sa[w] = a; sb[w] = b; }
    __syncthreads();
    if (threadIdx.x == 0) {
        float ta = 0.f, tb = 0.f;
        #pragma unroll
        for (int i = 0; i < 4; i++) { ta += sa[i]; tb += sb[i]; }
        sa[0] = ta; sb[0] = tb;
    }
    __syncthreads();
    a = sa[0]; b = sb[0];
}

// ---------------- c0 = u1 @ beta2, c1 = u1 @ gamma2 -----------------------
__global__ void __launch_bounds__(128) lnc_kernel(const float* __restrict__ u1,
                                                  const float* __restrict__ g2,
                                                  const float* __restrict__ b2,
                                                  float* __restrict__ c0,
                                                  float* __restrict__ c1)
{
    int j = blockIdx.x;
    float s0 = 0.f, s1 = 0.f;
    if (j < RANK) {
        const float* row = u1 + (size_t)j * CDIM;
        for (int c = threadIdx.x; c < CDIM; c += 128) {
            float u = row[c];
            s0 += u * b2[c];
            s1 += u * g2[c];
        }
    }
    blockReduce2(s0, s1);
    if (threadIdx.x == 0) { c0[j] = s0; c1[j] = s1; }
}

// ---------------- LN1 stats only ----------------
__global__ void __launch_bounds__(128) ln1_stats(const float* __restrict__ x,
                                                 float* __restrict__ stats)
{
    size_t row = blockIdx.x;
    const float* xr = x + row * CDIM;
    float s = 0.f, ss = 0.f;
    #pragma unroll
    for (int i = 0; i < 8; i++) {
        int c = threadIdx.x + i * 128;
        float v = (c < CDIM) ? xr[c] : 0.f;
        s += v; ss += v * v;
    }
    blockReduce2(s, ss);
    if (threadIdx.x == 0) {
        float mean = s * (1.f / CDIM);
        float var  = ss * (1.f / CDIM) - mean * mean;
        stats[row * 2]     = mean;
        stats[row * 2 + 1] = rsqrtf(var + 1e-5f);
    }
}

// ---------------- LN2 stats from fp16 filt ----------------
__global__ void __launch_bounds__(128) ln2_stats(const __half* __restrict__ in,
                                                 float* __restrict__ stats)
{
    size_t row = blockIdx.x;
    const __half* xr = in + row * CPAD;
    float s = 0.f, ss = 0.f;
    #pragma unroll
    for (int i = 0; i < 8; i++) {
        int c = threadIdx.x + i * 128;
        float v = (c < CDIM) ? __half2float(xr[c]) : 0.f;
        s += v; ss += v * v;
    }
    blockReduce2(s, ss);
    if (threadIdx.x == 0) {
        float mean = s * (1.f / CDIM);
        float var  = ss * (1.f / CDIM) - mean * mean;
        stats[row * 2]     = mean;
        stats[row * 2 + 1] = rsqrtf(var + 1e-5f);
    }
}

// ---------------- fused LN1-normalize + 3D spectral filter (sym DFT) ------
// No sR staging: S1 reads x from global and applies LN inline (each element
// consumed exactly once). smem 56.7KB -> 4 CTAs/SM (occ 25% -> 50%).
#define FCH 12
#define FFT_SMEM_FLOATS (2*495*FCH + 2*(45+121+81) + 2*891 + 2*FCH)

__global__ void __launch_bounds__(256) fft_filter_kernel(const float* __restrict__ xin,
                                                         const float* __restrict__ stats,
                                                         const float* __restrict__ g1,
                                                         const float* __restrict__ b1,
                                                         const float* __restrict__ cw,
                                                         __half* __restrict__ yout)
{
    extern __shared__ float sm[];
    float* sCr = sm;
    float* sCi = sCr + 495 * FCH;
    float* cD  = sCi + 495 * FCH;
    float* sD  = cD + 45;
    float* cWt = sD + 45;
    float* sWt = cWt + 121;
    float* cHt = sWt + 121;
    float* sHt = cHt + 81;
    float* sSt = sHt + 81;
    float* sG  = sSt + 2 * 891;
    float* sB  = sG + FCH;

    int tid = threadIdx.x;
    int b   = blockIdx.y;
    int c0  = blockIdx.x * FCH;

    for (int i = tid; i < 45; i += 256) {
        int kd = i / 9, d = i % 9; float s, c;
        sincospif(2.f * (float)(kd * d) / 9.f, &s, &c);
        cD[i] = c; sD[i] = s;
    }
    for (int i = tid; i < 121; i += 256) {
        int j = i / 11, k = i % 11; float s, c;
        sincospif(2.f * (float)(j * k) / 11.f, &s, &c);
        cWt[i] = c; sWt[i] = s;
    }
    for (int i = tid; i < 81; i += 256) {
        int j = i / 9, k = i % 9; float s, c;
        sincospif(2.f * (float)(j * k) / 9.f, &s, &c);
        cHt[i] = c; sHt[i] = s;
    }
    for (int i = tid; i < 2 * 891; i += 256)
        sSt[i] = stats[(size_t)b * NSPAT * 2 + i];
    if (tid < FCH) { sG[tid] = g1[c0 + tid]; sB[tid] = b1[c0 + tid]; }
    __syncthreads();

    const float* src = xin + ((size_t)b * NSPAT) * CDIM + c0;

    // S1: LN-on-load + rfft along D (real 9 -> 5 complex), folded
    for (int l = tid; l < 99 * FCH; l += 256) {
        int hw = l / FCH, cc = l - hw * FCH;
        const float* gbase = src + (size_t)(hw * 9) * CDIM + cc;
        float gm2 = sG[cc], bt2 = sB[cc];
        float xr[9];
        #pragma unroll
        for (int d = 0; d < 9; d++) {
            int n = hw * 9 + d;
            float raw = gbase[(size_t)d * CDIM];
            xr[d] = (raw - sSt[n * 2]) * sSt[n * 2 + 1] * gm2 + bt2;
        }
        float sp[4], smd[4];
        #pragma unroll
        for (int i = 0; i < 4; i++) { sp[i] = xr[i + 1] + xr[8 - i]; smd[i] = xr[i + 1] - xr[8 - i]; }
        #pragma unroll
        for (int kd = 0; kd < 5; kd++) {
            float re = xr[0], im = 0.f;
            #pragma unroll
            for (int i = 0; i < 4; i++) {
                re += sp[i]  * cD[kd * 9 + i + 1];
                im -= smd[i] * sD[kd * 9 + i + 1];
            }
            sCr[(hw * 5 + kd) * FCH + cc] = re;
            sCi[(hw * 5 + kd) * FCH + cc] = im;
        }
    }
    __syncthreads();

    // S2: forward FFT along W (11 pt), double-folded
    for (int l = tid; l < 9 * 5 * FCH; l += 256) {
        int h = l / (5 * FCH); int r = l - h * (5 * FCH); int kd = r / FCH, cc = r - kd * FCH;
        float ar[11], ai[11];
        #pragma unroll
        for (int w = 0; w < 11; w++) {
            int p = ((h * 11 + w) * 5 + kd) * FCH + cc;
            ar[w] = sCr[p]; ai[w] = sCi[p];
        }
        float arp[5], arm[5], aip[5], aim[5];
        #pragma unroll
        for (int k = 0; k < 5; k++) {
            arp[k] = ar[k + 1] + ar[10 - k]; arm[k] = ar[k + 1] - ar[10 - k];
            aip[k] = ai[k + 1] + ai[10 - k]; aim[k] = ai[k + 1] - ai[10 - k];
        }
        {
            float re0 = ar[0] + arp[0] + arp[1] + arp[2] + arp[3] + arp[4];
            float im0 = ai[0] + aip[0] + aip[1] + aip[2] + aip[3] + aip[4];
            int p = ((h * 11 + 0) * 5 + kd) * FCH + cc;
            sCr[p] = re0; sCi[p] = im0;
        }
        #pragma unroll
        for (int jp = 1; jp <= 5; jp++) {
            float A = ar[0], C = ai[0], B = 0.f, D = 0.f;
            #pragma unroll
            for (int k = 1; k <= 5; k++) {
                float c = cWt[jp * 11 + k], s = sWt[jp * 11 + k];
                A += arp[k - 1] * c;  D += arm[k - 1] * s;
                C += aip[k - 1] * c;  B += aim[k - 1] * s;
            }
            int p1 = ((h * 11 + jp) * 5 + kd) * FCH + cc;
            int p2 = ((h * 11 + (11 - jp)) * 5 + kd) * FCH + cc;
            sCr[p1] = A + B; sCi[p1] = C - D;
            sCr[p2] = A - B; sCi[p2] = C + D;
        }
    }
    __syncthreads();

    // S3: forward FFT along H (9 pt), double-folded
    for (int l = tid; l < 11 * 5 * FCH; l += 256) {
        int w = l / (5 * FCH); int r = l - w * (5 * FCH); int kd = r / FCH, cc = r - kd * FCH;
        float ar[9], ai[9];
        #pragma unroll
        for (int h = 0; h < 9; h++) {
            int p = ((h * 11 + w) * 5 + kd) * FCH + cc;
            ar[h] = sCr[p]; ai[h] = sCi[p];
        }
        float arp[4], arm[4], aip[4], aim[4];
        #pragma unroll
        for (int k = 0; k < 4; k++) {
            arp[k] = ar[k + 1] + ar[8 - k]; arm[k] = ar[k + 1] - ar[8 - k];
            aip[k] = ai[k + 1] + ai[8 - k]; aim[k] = ai[k + 1] - ai[8 - k];
        }
        {
            float re0 = ar[0] + arp[0] + arp[1] + arp[2] + arp[3];
            float im0 = ai[0] + aip[0] + aip[1] + aip[2] + aip[3];
            int p = ((0 * 11 + w) * 5 + kd) * FCH + cc;
            sCr[p] = re0; sCi[p] = im0;
        }
        #pragma unroll
        for (int jp = 1; jp <= 4; jp++) {
            float A = ar[0], C = ai[0], B = 0.f, D = 0.f;
            #pragma unroll
            for (int k = 1; k <= 4; k++) {
                float c = cHt[jp * 9 + k], s = sHt[jp * 9 + k];
                A += arp[k - 1] * c;  D += arm[k - 1] * s;
                C += aip[k - 1] * c;  B += aim[k - 1] * s;
            }
            int p1 = ((jp * 11 + w) * 5 + kd) * FCH + cc;
            int p2 = (((9 - jp) * 11 + w) * 5 + kd) * FCH + cc;
            sCr[p1] = A + B; sCi[p1] = C - D;
            sCr[p2] = A - B; sCi[p2] = C + D;
        }
    }
    __syncthreads();

    // weight multiply (ortho 1/891 folded in)
    {
        const float scl = 1.f / 891.f;
        for (int i = tid; i < 495 * FCH; i += 256) {
            int f = i / FCH, cc = i - f * FCH;
            size_t wi = ((size_t)f * CDIM + c0 + cc) * 2;
            float wr = cw[wi] * scl, wim = cw[wi + 1] * scl;
            float xr = sCr[i], xi = sCi[i];
            sCr[i] = xr * wr - xi * wim;
            sCi[i] = xr * wim + xi * wr;
        }
    }
    __syncthreads();

    // inverse FFT along H
    for (int l = tid; l < 11 * 5 * FCH; l += 256) {
        int w = l / (5 * FCH); int r = l - w * (5 * FCH); int kd = r / FCH, cc = r - kd * FCH;
        float ar[9], ai[9];
        #pragma unroll
        for (int h = 0; h < 9; h++) {
            int p = ((h * 11 + w) * 5 + kd) * FCH + cc;
            ar[h] = sCr[p]; ai[h] = sCi[p];
        }
        float arp[4], arm[4], aip[4], aim[4];
        #pragma unroll
        for (int k = 0; k < 4; k++) {
            arp[k] = ar[k + 1] + ar[8 - k]; arm[k] = ar[k + 1] - ar[8 - k];
            aip[k] = ai[k + 1] + ai[8 - k]; aim[k] = ai[k + 1] - ai[8 - k];
        }
        {
            float re0 = ar[0] + arp[0] + arp[1] + arp[2] + arp[3];
            float im0 = ai[0] + aip[0] + aip[1] + aip[2] + aip[3];
            int p = ((0 * 11 + w) * 5 + kd) * FCH + cc;
            sCr[p] = re0; sCi[p] = im0;
        }
        #pragma unroll
        for (int jp = 1; jp <= 4; jp++) {
            float A = ar[0], C = ai[0], B = 0.f, D = 0.f;
            #pragma unroll
            for (int k = 1; k <= 4; k++) {
                float c = cHt[jp * 9 + k], s = sHt[jp * 9 + k];
                A += arp[k - 1] * c;  D += arm[k - 1] * s;
                C += aip[k - 1] * c;  B += aim[k - 1] * s;
            }
            int p1 = ((jp * 11 + w) * 5 + kd) * FCH + cc;
            int p2 = (((9 - jp) * 11 + w) * 5 + kd) * FCH + cc;
            sCr[p1] = A - B; sCi[p1] = C + D;
            sCr[p2] = A + B; sCi[p2] = C - D;
        }
    }
    __syncthreads();

    // inverse FFT along W
    for (int l = tid; l < 9 * 5 * FCH; l += 256) {
        int h = l / (5 * FCH); int r = l - h * (5 * FCH); int kd = r / FCH, cc = r - kd * FCH;
        float ar[11], ai[11];
        #pragma unroll
        for (int w = 0; w < 11; w++) {
            int p = ((h * 11 + w) * 5 + kd) * FCH + cc;
            ar[w] = sCr[p]; ai[w] = sCi[p];
        }
        float arp[5], arm[5], aip[5], aim[5];
        #pragma unroll
        for (int k = 0; k < 5; k++) {
            arp[k] = ar[k + 1] + ar[10 - k]; arm[k] = ar[k + 1] - ar[10 - k];
            aip[k] = ai[k + 1] + ai[10 - k]; aim[k] = ai[k + 1] - ai[10 - k];
        }
        {
            float re0 = ar[0] + arp[0] + arp[1] + arp[2] + arp[3] + arp[4];
            float im0 = ai[0] + aip[0] + aip[1] + aip[2] + aip[3] + aip[4];
            int p = ((h * 11 + 0) * 5 + kd) * FCH + cc;
            sCr[p] = re0; sCi[p] = im0;
        }
        #pragma unroll
        for (int jp = 1; jp <= 5; jp++) {
            float A = ar[0], C = ai[0], B = 0.f, D = 0.f;
            #pragma unroll
            for (int k = 1; k <= 5; k++) {
                float c = cWt[jp * 11 + k], s = sWt[jp * 11 + k];
                A += arp[k - 1] * c;  D += arm[k - 1] * s;
                C += aip[k - 1] * c;  B += aim[k - 1] * s;
            }
            int p1 = ((h * 11 + jp) * 5 + kd) * FCH + cc;
            int p2 = ((h * 11 + (11 - jp)) * 5 + kd) * FCH + cc;
            sCr[p1] = A - B; sCi[p1] = C + D;
            sCr[p2] = A + B; sCi[p2] = C - D;
        }
    }
    __syncthreads();

    // irfft along D -> global fp16 (row stride CPAD)
    __half* dst = yout + ((size_t)b * NSPAT) * CPAD + c0;
    for (int l = tid; l < 99 * FCH; l += 256) {
        int hw = l / FCH, cc = l - hw * FCH;
        float Xr[5], Xi[5];
        #pragma unroll
        for (int kd = 0; kd < 5; kd++) {
            int p = (hw * 5 + kd) * FCH + cc;
            Xr[kd] = sCr[p]; Xi[kd] = sCi[p];
        }
        float t0 = Xr[0];
        dst[(size_t)(hw * 9 + 0) * CPAD + cc] =
            __float2half(t0 + 2.f * (Xr[1] + Xr[2] + Xr[3] + Xr[4]));
        #pragma unroll
        for (int dp = 1; dp <= 4; dp++) {
            float P = 0.f, Q = 0.f;
            #pragma unroll
            for (int k = 1; k <= 4; k++) {
                P += Xr[k] * cD[k * 9 + dp];
                Q += Xi[k] * sD[k * 9 + dp];
            }
            dst[(size_t)(hw * 9 + dp) * CPAD + cc]       = __float2half(t0 + 2.f * (P - Q));
            dst[(size_t)(hw * 9 + (9 - dp)) * CPAD + cc] = __float2half(t0 + 2.f * (P + Q));
        }
    }
}

// ---------------- mma.sync GEMM (R13 config) ------------------------------
// epi 0: half | epi 1: +bias, gelu, half | epi 2: +bias +residual, float |
// epi 3: LN2-folded: out = inv*acc + c0 - inv*mean*c1, half
#define GS      3
#define STAGEB  32768
#define GEMM_SMEM (GS*STAGEB)

__device__ __forceinline__ void load_stage(
    const __half* __restrict__ A, int lda,
    const __half* __restrict__ B, int ldb,
    int mBase, int nBase, uint32_t data0, int sn, int kt, int tid)
{
    uint32_t sbase = data0 + sn * STAGEB;
    #pragma unroll
    for (int j = 0; j < 8; j++) {
        int ci = tid + j * 256;
        int v  = ci & 1023;
        int row = v >> 3;
        int cb  = (v & 7) << 4;
        const __half* g;
        uint32_t dst;
        if (ci < 1024) {
            g   = A + (size_t)(mBase + row) * lda + kt * 64 + (cb >> 1);
            dst = sbase + SWZ128(row * 128 + cb);
        } else {
            g   = B + (size_t)(nBase + row) * ldb + kt * 64 + (cb >> 1);
            dst = sbase + 16384 + SWZ128(row * 128 + cb);
        }
        cp_async16(dst, g);
    }
}

__global__ void __launch_bounds__(256, 2) gemm_mma(
    const __half* __restrict__ A, int lda,
    const __half* __restrict__ B, int ldb,
    __half* outH, int ldo,
    float* outF,
    const float* __restrict__ bias,       // epi1/2: bias; epi3: c0
    const float* __restrict__ resid,      // epi2: residual
    const float* __restrict__ c1v,        // epi3: c1
    const float* __restrict__ stats2,     // epi3: per-row (mean, inv)
    int Nvalid, int KT, int epi, int Mvalid)
{
    extern __shared__ __align__(1024) char smem[];
    uint32_t data0 = smem_u32(smem);

    int tid   = threadIdx.x;
    int lane  = tid & 31;
    int warp  = tid >> 5;
    int wm    = warp >> 2;
    int wn    = warp & 3;
    int nBase = blockIdx.x * 128;
    int mBase = blockIdx.y * 128;

    int mi  = lane >> 3, rin = lane & 7;
    int rowA = wm * 64 + (mi & 1) * 8 + rin;
    int colA = (mi >> 1) * 16;
    int rowB = wn * 32 + (mi >> 1) * 8 + rin;
    int colB = (mi & 1) * 16;

    float cAcc[4][4][4];
    #pragma unroll
    for (int m = 0; m < 4; m++)
        #pragma unroll
        for (int n = 0; n < 4; n++)
            #pragma unroll
            for (int r = 0; r < 4; r++) cAcc[m][n][r] = 0.f;

    load_stage(A, lda, B, ldb, mBase, nBase, data0, 0, 0, tid);
    cp_commit();
    load_stage(A, lda, B, ldb, mBase, nBase, data0, 1, 1, tid);
    cp_commit();

    int s = 0;
    for (int k = 0; k < KT; k++) {
        cp_wait1();
        __syncthreads();

        int kn = k + 2;
        if (kn < KT) {
            int sn = s + 2; if (sn >= GS) sn -= GS;
            load_stage(A, lda, B, ldb, mBase, nBase, data0, sn, kn, tid);
        }
        cp_commit();

        uint32_t As = data0 + s * STAGEB;
        uint32_t Bs = As + 16384;
        #pragma unroll
        for (int kk = 0; kk < 4; kk++) {
            uint32_t a[4][4];
            #pragma unroll
            for (int m = 0; m < 4; m++) {
                uint32_t br = (uint32_t)(rowA + m * 16) * 128;
                uint32_t xv = (br >> 3) & 0x70;
                ldsm4(a[m][0], a[m][1], a[m][2], a[m][3],
                      As + br + ((kk * 32 + colA) ^ xv));
            }
            uint32_t b[4][2];
            #pragma unroll
            for (int np = 0; np < 2; np++) {
                uint32_t br = (uint32_t)(rowB + np * 16) * 128;
                uint32_t xv = (br >> 3) & 0x70;
                uint32_t r0, r1, r2, r3;
                ldsm4(r0, r1, r2, r3, Bs + br + ((kk * 32 + colB) ^ xv));
                b[np * 2][0] = r0; b[np * 2][1] = r1;
                b[np * 2 + 1][0] = r2; b[np * 2 + 1][1] = r3;
            }
            #pragma unroll
            for (int m = 0; m < 4; m++)
                #pragma unroll
                for (int n = 0; n < 4; n++)
                    mma16816(cAcc[m][n], a[m], b[n]);
        }

        s++; if (s == GS) s = 0;
    }

    // epilogue
    int r0 = lane >> 2, c0c = (lane & 3) * 2;
    #pragma unroll
    for (int m = 0; m < 4; m++) {
        #pragma unroll
        for (int n = 0; n < 4; n++) {
            int gnc = nBase + wn * 32 + n * 8 + c0c;
            #pragma unroll
            for (int h = 0; h < 2; h++) {
                int gm = mBase + wm * 64 + m * 16 + r0 + h * 8;
                float v0 = cAcc[m][n][h * 2 + 0];
                float v1 = cAcc[m][n][h * 2 + 1];
                if (epi == 0) {
                    *(__half2*)(outH + (size_t)gm * ldo + gnc) = __floats2half2_rn(v0, v1);
                } else if (epi == 1) {
                    float o0 = 0.f, o1 = 0.f;
                    if (gnc < Nvalid) {
                        float t = v0 + bias[gnc];
                        o0 = 0.5f * t * (1.f + erff(t * 0.70710678118654752f));
                    }
                    if (gnc + 1 < Nvalid) {
                        float t = v1 + bias[gnc + 1];
                        o1 = 0.5f * t * (1.f + erff(t * 0.70710678118654752f));
                    }
                    *(__half2*)(outH + (size_t)gm * ldo + gnc) = __floats2half2_rn(o0, o1);
                } else if (epi == 3) {
                    float mean = stats2[(size_t)gm * 2];
                    float inv  = stats2[(size_t)gm * 2 + 1];
                    float sm_  = inv * mean;
                    float o0 = inv * v0 + bias[gnc]     - sm_ * c1v[gnc];
                    float o1 = inv * v1 + bias[gnc + 1] - sm_ * c1v[gnc + 1];
                    *(__half2*)(outH + (size_t)gm * ldo + gnc) = __floats2half2_rn(o0, o1);
                } else {
                    if (gm < Mvalid) {
                        if (gnc < Nvalid)
                            outF[(size_t)gm * Nvalid + gnc] =
                                v0 + bias[gnc] + resid[(size_t)gm * Nvalid + gnc];
                        if (gnc + 1 < Nvalid)
                            outF[(size_t)gm * Nvalid + gnc + 1] =
                                v1 + bias[gnc + 1] + resid[(size_t)gm * Nvalid + gnc + 1];
                    }
                }
            }
        }
    }
}

// ---------------- launcher ----------------
extern "C" void kernel_launch(void* const* d_in, const int* in_sizes, int n_in,
                              void* d_out, int out_size)
{
    (void)in_sizes; (void)n_in; (void)out_size;
    const float* x   = (const float*)d_in[0];
    const float* cw  = (const float*)d_in[1];
    const float* g1  = (const float*)d_in[2];
    const float* b1  = (const float*)d_in[3];
    const float* g2  = (const float*)d_in[4];
    const float* b2  = (const float*)d_in[5];
    const float* u1w = (const float*)d_in[6];
    const float* v1w = (const float*)d_in[7];
    const float* v1b = (const float*)d_in[8];
    const float* u2w = (const float*)d_in[9];
    const float* v2w = (const float*)d_in[10];
    const float* v2b = (const float*)d_in[11];
    float* out = (float*)d_out;

    void *p_st, *p_st2, *p_c0, *p_c1, *p_fh, *p_a1, *p_h1, *p_a2, *p_u1, *p_v1, *p_u2, *p_v2;
    cudaGetSymbolAddress(&p_st,  g_stats);
    cudaGetSymbolAddress(&p_st2, g_stats2);
    cudaGetSymbolAddress(&p_c0,  g_c0);
    cudaGetSymbolAddress(&p_c1,  g_c1);
    cudaGetSymbolAddress(&p_fh,  g_filth);
    cudaGetSymbolAddress(&p_a1,  g_a1);
    cudaGetSymbolAddress(&p_h1,  g_h1);
    cudaGetSymbolAddress(&p_a2,  g_a2);
    cudaGetSymbolAddress(&p_u1,  g_u1h);
    cudaGetSymbolAddress(&p_v1,  g_v1h);
    cudaGetSymbolAddress(&p_u2,  g_u2h);
    cudaGetSymbolAddress(&p_v2,  g_v2h);

    cudaFuncSetAttribute(fft_filter_kernel, cudaFuncAttributeMaxDynamicSharedMemorySize,
                         FFT_SMEM_FLOATS * 4);
    cudaFuncSetAttribute(gemm_mma, cudaFuncAttributeMaxDynamicSharedMemorySize, GEMM_SMEM);

    convert_all<<<(CVT_S4 + 255) / 256, 256>>>(u1w, v1w, u2w, v2w, g2,
        (__half*)p_u1, (__half*)p_v1, (__half*)p_u2, (__half*)p_v2);

    lnc_kernel<<<RPAD, 128>>>(u1w, g2, b2, (float*)p_c0, (float*)p_c1);

    ln1_stats<<<MTOK, 128>>>(x, (float*)p_st);

    fft_filter_kernel<<<dim3(CDIM / FCH, BATCH), 256, FFT_SMEM_FLOATS * 4>>>(
        x, (const float*)p_st, g1, b1, cw, (__half*)p_fh);

    ln2_stats<<<MTOK, 128>>>((const __half*)p_fh, (float*)p_st2);

    // z1 = LN2-folded: inv*(filt @ (u1.g2)^T) + c0 - inv*mean*c1   (epi 3)
    gemm_mma<<<dim3(RPAD / 128, MPAD / 128), 256, GEMM_SMEM>>>(
        (const __half*)p_fh, CPAD, (const __half*)p_u1, CPAD,
        (__half*)p_a1, RPAD, nullptr, (const float*)p_c0, nullptr,
        (const float*)p_c1, (const float*)p_st2, RANK, 15, 3, MTOK);

    // h = gelu(z1 @ v1^T + b)
    gemm_mma<<<dim3(HPAD / 128, MPAD / 128), 256, GEMM_SMEM>>>(
        (const __half*)p_a1, RPAD, (const __half*)p_v1, RPAD,
        (__half*)p_h1, HPAD, nullptr, v1b, nullptr, nullptr, nullptr,
        HID, RPAD / 64, 1, MTOK);

    // z2 = h @ u2^T  (29 K-tiles)
    gemm_mma<<<dim3(RPAD / 128, MPAD / 128), 256, GEMM_SMEM>>>(
        (const __half*)p_h1, HPAD, (const __half*)p_u2, HPAD,
        (__half*)p_a2, RPAD, nullptr, nullptr, nullptr, nullptr, nullptr,
        RANK, 29, 0, MTOK);

    // out = z2 @ v2^T + b + x
    gemm_mma<<<dim3(CPAD / 128, MPAD / 128), 256, GEMM_SMEM>>>(
        (const __half*)p_a2, RPAD, (const __half*)p_v2, RPAD,
        nullptr, CDIM, out, v2b, x, nullptr, nullptr,
        CDIM, RPAD / 64, 2, MTOK);
}